// round 6
// baseline (speedup 1.0000x reference)
#include <cuda_runtime.h>
#include <cuda_bf16.h>
#include <cstdint>
#include <math.h>

#define NN 10000
#define EE 320000
#define DD 128

// ================= static device scratch =================
__device__ float g_proj[8][NN * DD];          // V1h V2h P1h P2h P3h D1h D2h Th
__device__ float g_enew[(size_t)EE * DD];
__device__ float g_facc[NN * DD];
__device__ int   g_cnt0[NN];
__device__ int   g_mlist[EE];
__device__ int   g_mcount;
// pre-split weight tiles in swizzled layout (32KB each):
// slots 0..6 node W (V1,V2,P1,P2,P3,D1,D2), 7 E1, 8 V, 9/10 = W_T halves
__device__ __align__(16) unsigned char g_wbh[11 * 32768];
__device__ __align__(16) unsigned char g_wbl[11 * 32768];

__device__ __forceinline__ float lrelu(float x) { return x > 0.f ? x : 0.01f * x; }
__device__ __forceinline__ float relu_(float x) { return x > 0.f ? x : 0.f; }

__device__ __forceinline__ uint32_t smem_u32(const void* p) {
    uint32_t a;
    asm("{ .reg .u64 t; cvta.to.shared.u64 t, %1; cvt.u32.u64 %0, t; }" : "=r"(a) : "l"(p));
    return a;
}
__device__ __forceinline__ uint32_t pack2(__nv_bfloat16 a, __nv_bfloat16 b) {
    __nv_bfloat162 t; t.x = a; t.y = b;
    return *reinterpret_cast<uint32_t*>(&t);
}

// swizzled byte offset inside a 128x128 bf16 tile (B tiles): row stride 256B
__device__ __forceinline__ uint32_t soff(int r, int c) {
    return (uint32_t)((r << 8) + ((((c >> 3) ^ (r & 7)) << 4) | ((c & 7) << 1)));
}
// swizzled byte offset inside a 128x64 bf16 tile (A half-tiles): row stride 128B
__device__ __forceinline__ uint32_t soff64(int r, int c) {
    return (uint32_t)((r << 7) + (((((c >> 3) ^ (r & 7)) & 7) << 4) | ((c & 7) << 1)));
}

__device__ __forceinline__ void ldsm4(uint32_t* r, uint32_t addr) {
    asm volatile("ldmatrix.sync.aligned.m8n8.x4.shared.b16 {%0,%1,%2,%3}, [%4];"
                 : "=r"(r[0]), "=r"(r[1]), "=r"(r[2]), "=r"(r[3]) : "r"(addr));
}
__device__ __forceinline__ void mma16816(float* d, const uint32_t* a,
                                         uint32_t b0, uint32_t b1) {
    asm volatile(
        "mma.sync.aligned.m16n8k16.row.col.f32.bf16.bf16.f32 "
        "{%0,%1,%2,%3}, {%4,%5,%6,%7}, {%8,%9}, {%0,%1,%2,%3};"
        : "+f"(d[0]), "+f"(d[1]), "+f"(d[2]), "+f"(d[3])
        : "r"(a[0]), "r"(a[1]), "r"(a[2]), "r"(a[3]), "r"(b0), "r"(b1));
}

// split 8 fp32 -> hi/lo bf16x2 quads
__device__ __forceinline__ void cvt8(float4 v0, float4 v1, uint4& hi, uint4& lo) {
    __nv_bfloat16 a0 = __float2bfloat16(v0.x), a1 = __float2bfloat16(v0.y);
    __nv_bfloat16 a2 = __float2bfloat16(v0.z), a3 = __float2bfloat16(v0.w);
    __nv_bfloat16 a4 = __float2bfloat16(v1.x), a5 = __float2bfloat16(v1.y);
    __nv_bfloat16 a6 = __float2bfloat16(v1.z), a7 = __float2bfloat16(v1.w);
    hi.x = pack2(a0, a1); hi.y = pack2(a2, a3);
    hi.z = pack2(a4, a5); hi.w = pack2(a6, a7);
    lo.x = pack2(__float2bfloat16(v0.x - __bfloat162float(a0)),
                 __float2bfloat16(v0.y - __bfloat162float(a1)));
    lo.y = pack2(__float2bfloat16(v0.z - __bfloat162float(a2)),
                 __float2bfloat16(v0.w - __bfloat162float(a3)));
    lo.z = pack2(__float2bfloat16(v1.x - __bfloat162float(a4)),
                 __float2bfloat16(v1.y - __bfloat162float(a5)));
    lo.w = pack2(__float2bfloat16(v1.z - __bfloat162float(a6)),
                 __float2bfloat16(v1.w - __bfloat162float(a7)));
}

// shared memory layout (102400 bytes total -> 2 CTAs/SM)
#define SM_BIAS 0
#define SM_ROWA 512     /* per-row src  */
#define SM_ROWB 1024    /* per-row dst  */
#define SM_ROWC 1536    /* per-row mask / eid */
#define SM_SV   2048    /* 2 x 128 partial row sums */
#define SM_AH   4096                 /* 128x64 bf16 hi  (16KB) */
#define SM_AL   (4096 + 16384)       /* 128x64 bf16 lo  (16KB) */
#define SM_BH   (4096 + 32768)       /* 128x128 bf16 hi (32KB) */
#define SM_BL   (4096 + 65536)       /* 128x128 bf16 lo (32KB) */
#define SM_TOTAL (4096 + 98304)

// ---- 3-term split GEMM over one K-half, warp tile 32(M) x 64(N), 8 warps ----
// wm = wid&3 (M block of 32), wn = wid>>2 (N half of 64)
// acc[mf][2*bn+p][*]: rows wm*32+mf*16+(lane>>2){,+8}, cols wn*64+bn*16+p*8..+7
__device__ __forceinline__ void gemm_half(uint32_t smb, int lane, int wm, int wn,
                                          int kh, float (&acc)[2][8][4]) {
    const int fr = lane & 15;
    const int fc = (lane >> 4) << 3;
    const int m0 = wm * 32;
    const int n0 = wn * 64;
#pragma unroll
    for (int ks = 0; ks < 4; ks++) {
        uint32_t aH[2][4], aL[2][4];
#pragma unroll
        for (int mf = 0; mf < 2; mf++) {
            ldsm4(aH[mf], smb + SM_AH + soff64(m0 + mf * 16 + fr, ks * 16 + fc));
            ldsm4(aL[mf], smb + SM_AL + soff64(m0 + mf * 16 + fr, ks * 16 + fc));
        }
        const int kc = kh * 64 + ks * 16 + fc;
#pragma unroll
        for (int bn = 0; bn < 4; bn++) {
            uint32_t bH[4], bL[4];
            ldsm4(bH, smb + SM_BH + soff(n0 + bn * 16 + fr, kc));
            ldsm4(bL, smb + SM_BL + soff(n0 + bn * 16 + fr, kc));
#pragma unroll
            for (int mf = 0; mf < 2; mf++) {
                mma16816(acc[mf][2 * bn],     aH[mf], bH[0], bH[2]);
                mma16816(acc[mf][2 * bn + 1], aH[mf], bH[1], bH[3]);
                mma16816(acc[mf][2 * bn],     aL[mf], bH[0], bH[2]);
                mma16816(acc[mf][2 * bn + 1], aL[mf], bH[1], bH[3]);
                mma16816(acc[mf][2 * bn],     aH[mf], bL[0], bL[2]);
                mma16816(acc[mf][2 * bn + 1], aH[mf], bL[1], bL[3]);
            }
        }
    }
}

__device__ __forceinline__ void copy_B(char* sm, int slot, int tid) {
    const uint4* gh = (const uint4*)(g_wbh + slot * 32768);
    const uint4* gl = (const uint4*)(g_wbl + slot * 32768);
    uint4* bh = (uint4*)(sm + SM_BH);
    uint4* bl = (uint4*)(sm + SM_BL);
    for (int i = tid; i < 2048; i += 256) { bh[i] = gh[i]; bl[i] = gl[i]; }
}

// ================= prep kernels =================
__global__ void k_zero() {
    int i = blockIdx.x * blockDim.x + threadIdx.x;
    int stride = gridDim.x * blockDim.x;
    for (int t = i; t < NN * DD; t += stride) g_facc[t] = 0.f;
    for (int t = i; t < NN; t += stride) g_cnt0[t] = 0;
    if (i == 0) g_mcount = 0;
}

// vectorized: one thread handles 8 consecutive k (one 16B swizzle chunk)
__global__ void k_wbf(const float* W0, const float* W1, const float* W2, const float* W3,
                      const float* W4, const float* W5, const float* W6, const float* W7,
                      const float* W8, const float* WT) {
    const float* Wp[9] = {W0, W1, W2, W3, W4, W5, W6, W7, W8};
    int i = blockIdx.x * blockDim.x + threadIdx.x;
    int stride = gridDim.x * blockDim.x;
    for (int t = i; t < 11 * 2048; t += stride) {
        int slot = t >> 11, r = t & 2047;
        int n = r >> 4, k8 = r & 15;
        const float* srcp;
        if (slot < 9) srcp = Wp[slot] + n * 128 + k8 * 8;
        else if (slot == 9) srcp = WT + n * 256 + k8 * 8;
        else srcp = WT + n * 256 + 128 + k8 * 8;
        float4 v0 = ((const float4*)srcp)[0];
        float4 v1 = ((const float4*)srcp)[1];
        uint4 hi, lo; cvt8(v0, v1, hi, lo);
        uint32_t off = (uint32_t)slot * 32768u + soff(n, k8 * 8);
        *reinterpret_cast<uint4*>(g_wbh + off) = hi;
        *reinterpret_cast<uint4*>(g_wbl + off) = lo;
    }
}

__global__ void k_count(const int* __restrict__ smask, const int* __restrict__ dst) {
    int e = blockIdx.x * 256 + threadIdx.x;
    int lane = threadIdx.x & 31;
    int sm_ = smask[e];
    int d_ = dst[e];
    unsigned bal = __ballot_sync(0xffffffffu, sm_ == 1);
    if (sm_ == 0) atomicAdd(&g_cnt0[d_], 1);
    int lead = bal ? (__ffs(bal) - 1) : 0;
    int basec = 0;
    if (bal && lane == lead) basec = atomicAdd(&g_mcount, __popc(bal));
    basec = __shfl_sync(0xffffffffu, basec, lead);
    if (sm_ == 1) g_mlist[basec + __popc(bal & ((1u << lane) - 1u))] = e;
}

// ================= node GEMMs (8 outputs) =================
__global__ void __launch_bounds__(256, 2)
k_nodeg(const float* __restrict__ h, const float* __restrict__ p,
        const float* __restrict__ dv,
        const float* bV1, const float* bV2, const float* bP1,
        const float* bP2, const float* bP3, const float* bD1,
        const float* bD2, const float* bT) {
    extern __shared__ char sm[];
    uint32_t smb = smem_u32(sm);
    int tid = threadIdx.x, lane = tid & 31, wid = tid >> 5;
    int wm = wid & 3, wn = wid >> 2;
    int pair = blockIdx.y;
    int r0 = blockIdx.x * 128;

    const float* X0;
    const float* bias;
    int slot0;
    switch (pair) {
        case 0: X0 = h;  slot0 = 0; bias = bV1; break;
        case 1: X0 = h;  slot0 = 1; bias = bV2; break;
        case 2: X0 = p;  slot0 = 2; bias = bP1; break;
        case 3: X0 = p;  slot0 = 3; bias = bP2; break;
        case 4: X0 = p;  slot0 = 4; bias = bP3; break;
        case 5: X0 = dv; slot0 = 5; bias = bD1; break;
        case 6: X0 = dv; slot0 = 6; bias = bD2; break;
        default: X0 = h; slot0 = 9; bias = bT; break;
    }
    if (tid < 128) ((float*)(sm + SM_BIAS))[tid] = bias[tid];

    float acc[2][8][4];
#pragma unroll
    for (int mf = 0; mf < 2; mf++)
#pragma unroll
        for (int j = 0; j < 8; j++)
#pragma unroll
            for (int i = 0; i < 4; i++) acc[mf][j][i] = 0.f;

    int nph = (pair == 7) ? 2 : 1;
    for (int ph = 0; ph < nph; ph++) {
        const float* X = (pair == 7 && ph == 1) ? dv : X0;
        copy_B(sm, slot0 + ph, tid);
        for (int kh = 0; kh < 2; kh++) {
            for (int u = tid; u < 1024; u += 256) {
                int row = u >> 3, ch = u & 7;
                int g = r0 + row;
                float4 v0 = make_float4(0.f, 0.f, 0.f, 0.f), v1 = v0;
                if (g < NN) {
                    v0 = ((const float4*)X)[(size_t)g * 32 + kh * 16 + ch * 2];
                    v1 = ((const float4*)X)[(size_t)g * 32 + kh * 16 + ch * 2 + 1];
                }
                uint4 hi, lo; cvt8(v0, v1, hi, lo);
                uint32_t off = soff64(row, ch * 8);
                *(uint4*)(sm + SM_AH + off) = hi;
                *(uint4*)(sm + SM_AL + off) = lo;
            }
            __syncthreads();
            gemm_half(smb, lane, wm, wn, kh, acc);
            __syncthreads();
        }
    }

    // direct register epilogue
    const float* bias_s = (const float*)(sm + SM_BIAS);
    float* outp = g_proj[pair];
    int q = lane >> 2, m = lane & 3;
#pragma unroll
    for (int mf = 0; mf < 2; mf++) {
        int r1 = r0 + wm * 32 + mf * 16 + q;
        int r2 = r1 + 8;
#pragma unroll
        for (int j = 0; j < 8; j++) {
            int col = wn * 64 + j * 8 + m * 2;
            float b0 = bias_s[col], b1 = bias_s[col + 1];
            if (r1 < NN)
                *(float2*)&outp[(size_t)r1 * DD + col] =
                    make_float2(acc[mf][j][0] + b0, acc[mf][j][1] + b1);
            if (r2 < NN)
                *(float2*)&outp[(size_t)r2 * DD + col] =
                    make_float2(acc[mf][j][2] + b0, acc[mf][j][3] + b1);
        }
    }
}

// ================= edge pass A: E1e GEMM + e_new + e' output =================
__global__ void __launch_bounds__(256, 2)
k_edgeA(const float* __restrict__ e_in, const int* __restrict__ src,
        const int* __restrict__ dst, const int* __restrict__ smask,
        const float* __restrict__ bE1, float* __restrict__ e_out) {
    extern __shared__ char sm[];
    uint32_t smb = smem_u32(sm);
    int tid = threadIdx.x, lane = tid & 31, wid = tid >> 5;
    int wm = wid & 3, wn = wid >> 2;
    int e0 = blockIdx.x * 128;

    if (tid < 128) {
        ((float*)(sm + SM_BIAS))[tid] = bE1[tid];
        int eg = e0 + tid;
        ((int*)(sm + SM_ROWA))[tid] = src[eg];
        ((int*)(sm + SM_ROWB))[tid] = dst[eg];
        ((int*)(sm + SM_ROWC))[tid] = smask[eg];
    }
    copy_B(sm, 7, tid);

    float acc[2][8][4];
#pragma unroll
    for (int mf = 0; mf < 2; mf++)
#pragma unroll
        for (int j = 0; j < 8; j++)
#pragma unroll
            for (int i = 0; i < 4; i++) acc[mf][j][i] = 0.f;

    for (int kh = 0; kh < 2; kh++) {
        for (int u = tid; u < 1024; u += 256) {
            int row = u >> 3, ch = u & 7;
            float4 v0 = ((const float4*)e_in)[(size_t)(e0 + row) * 32 + kh * 16 + ch * 2];
            float4 v1 = ((const float4*)e_in)[(size_t)(e0 + row) * 32 + kh * 16 + ch * 2 + 1];
            uint4 hi, lo; cvt8(v0, v1, hi, lo);
            uint32_t off = soff64(row, ch * 8);
            *(uint4*)(sm + SM_AH + off) = hi;
            *(uint4*)(sm + SM_AL + off) = lo;
        }
        __syncthreads();
        gemm_half(smb, lane, wm, wn, kh, acc);
        __syncthreads();
    }

    // direct register epilogue
    const float* bias_s = (const float*)(sm + SM_BIAS);
    const int* ssrc = (const int*)(sm + SM_ROWA);
    const int* sdst = (const int*)(sm + SM_ROWB);
    const int* smsk = (const int*)(sm + SM_ROWC);
    const float* P1 = g_proj[2];
    const float* P2 = g_proj[3];
    int q = lane >> 2, m = lane & 3;
#pragma unroll
    for (int mf = 0; mf < 2; mf++) {
#pragma unroll
        for (int rh = 0; rh < 2; rh++) {
            int lr = wm * 32 + mf * 16 + q + rh * 8;
            int eg = e0 + lr;
            int s = ssrc[lr], dd = sdst[lr], msk = smsk[lr];
            const float* p1r = P1 + (size_t)dd * DD;
            const float* p2r = P2 + (size_t)s * DD;
            const float* evr = e_in + (size_t)eg * DD;
            float* eor = e_out + (size_t)eg * DD;
            float* enr = g_enew + (size_t)eg * DD;
#pragma unroll
            for (int j = 0; j < 8; j++) {
                int col = wn * 64 + j * 8 + m * 2;
                float a0 = acc[mf][j][2 * rh], a1 = acc[mf][j][2 * rh + 1];
                float2 p1 = *(const float2*)&p1r[col];
                float2 p2 = *(const float2*)&p2r[col];
                float2 ev = *(const float2*)&evr[col];
                float2 en;
                en.x = 0.5f * (p1.x - p2.x + a0 + bias_s[col]);
                en.y = 0.5f * (p1.y - p2.y + a1 + bias_s[col + 1]);
                float2 o;
                o.x = ev.x + lrelu(en.x);
                o.y = ev.y + lrelu(en.y);
                *(float2*)&eor[col] = o;
                if (msk) *(float2*)&enr[col] = en;
            }
        }
    }
}

// ================= edge pass B: masked V GEMM + fab atomics =================
__global__ void __launch_bounds__(256, 2)
k_edgeB(const float* __restrict__ h, const float* __restrict__ bV,
        const int* __restrict__ src, const int* __restrict__ dst) {
    extern __shared__ char sm[];
    uint32_t smb = smem_u32(sm);
    int tid = threadIdx.x, lane = tid & 31, wid = tid >> 5;
    int wm = wid & 3, wn = wid >> 2;
    int mc = g_mcount;
    int base = blockIdx.x * 128;
    if (base >= mc) return;
    int nt = min(128, mc - base);

    int* seid = (int*)(sm + SM_ROWC);
    int* ssrc = (int*)(sm + SM_ROWA);
    int* sdst = (int*)(sm + SM_ROWB);
    if (tid < 128) {
        ((float*)(sm + SM_BIAS))[tid] = bV[tid];
        int eid = (tid < nt) ? g_mlist[base + tid] : -1;
        seid[tid] = eid;
        ssrc[tid] = (eid >= 0) ? src[eid] : 0;
        sdst[tid] = (eid >= 0) ? dst[eid] : 0;
    }
    copy_B(sm, 8, tid);
    __syncthreads();

    float acc[2][8][4];
#pragma unroll
    for (int mf = 0; mf < 2; mf++)
#pragma unroll
        for (int j = 0; j < 8; j++)
#pragma unroll
            for (int i = 0; i < 4; i++) acc[mf][j][i] = 0.f;

    for (int kh = 0; kh < 2; kh++) {
        for (int u = tid; u < 1024; u += 256) {
            int row = u >> 3, ch = u & 7;
            float4 v0 = make_float4(0.f, 0.f, 0.f, 0.f), v1 = v0;
            if (row < nt) {
                float4 hs0 = ((const float4*)h)[(size_t)ssrc[row] * 32 + kh * 16 + ch * 2];
                float4 hs1 = ((const float4*)h)[(size_t)ssrc[row] * 32 + kh * 16 + ch * 2 + 1];
                float4 hd0 = ((const float4*)h)[(size_t)sdst[row] * 32 + kh * 16 + ch * 2];
                float4 hd1 = ((const float4*)h)[(size_t)sdst[row] * 32 + kh * 16 + ch * 2 + 1];
                v0.x = hs0.x * hd0.x; v0.y = hs0.y * hd0.y;
                v0.z = hs0.z * hd0.z; v0.w = hs0.w * hd0.w;
                v1.x = hs1.x * hd1.x; v1.y = hs1.y * hd1.y;
                v1.z = hs1.z * hd1.z; v1.w = hs1.w * hd1.w;
            }
            uint4 hi, lo; cvt8(v0, v1, hi, lo);
            uint32_t off = soff64(row, ch * 8);
            *(uint4*)(sm + SM_AH + off) = hi;
            *(uint4*)(sm + SM_AL + off) = lo;
        }
        __syncthreads();
        gemm_half(smb, lane, wm, wn, kh, acc);
        __syncthreads();
    }

    // partial row-sums of relu(acc + bias): this warp covers cols wn*64..+63
    const float* bias_s = (const float*)(sm + SM_BIAS);
    int q = lane >> 2, m = lane & 3;
    float s[2][2] = {{0.f, 0.f}, {0.f, 0.f}};
#pragma unroll
    for (int mf = 0; mf < 2; mf++)
#pragma unroll
        for (int j = 0; j < 8; j++) {
            float b0 = bias_s[wn * 64 + j * 8 + m * 2];
            float b1 = bias_s[wn * 64 + j * 8 + m * 2 + 1];
            s[mf][0] += relu_(acc[mf][j][0] + b0) + relu_(acc[mf][j][1] + b1);
            s[mf][1] += relu_(acc[mf][j][2] + b0) + relu_(acc[mf][j][3] + b1);
        }
#pragma unroll
    for (int mf = 0; mf < 2; mf++) {
        s[mf][0] += __shfl_xor_sync(0xffffffffu, s[mf][0], 1);
        s[mf][0] += __shfl_xor_sync(0xffffffffu, s[mf][0], 2);
        s[mf][1] += __shfl_xor_sync(0xffffffffu, s[mf][1], 1);
        s[mf][1] += __shfl_xor_sync(0xffffffffu, s[mf][1], 2);
    }
    float* svb = (float*)(sm + SM_SV);
    if (m == 0) {
#pragma unroll
        for (int mf = 0; mf < 2; mf++) {
            svb[wn * 128 + wm * 32 + mf * 16 + q] = s[mf][0];
            svb[wn * 128 + wm * 32 + mf * 16 + q + 8] = s[mf][1];
        }
    }
    __syncthreads();

    if (tid < nt) {
        float sv = svb[tid] + svb[128 + tid];
        int eid = seid[tid];
        const float4* EN = (const float4*)g_enew + (size_t)eid * 32;
        float sq = 0.f;
#pragma unroll 8
        for (int k4 = 0; k4 < 32; k4++) {
            float4 en = EN[k4];
            sq += en.x * en.x + en.y * en.y + en.z * en.z + en.w * en.w;
        }
        float L = sqrtf(sq);
        if (L > 1e-9f && sv > 0.f) {
            float r = 0.5f * sqrtf(L);
            float cf = sv * expf(-r / 0.3f) / (1.2f * L * sqrtf(L));
            float* fp = &g_facc[(size_t)sdst[tid] * DD];
#pragma unroll 8
            for (int k4 = 0; k4 < 32; k4++) {
                float4 en = EN[k4];
                atomicAdd(fp + k4 * 4 + 0, cf * en.x);
                atomicAdd(fp + k4 * 4 + 1, cf * en.y);
                atomicAdd(fp + k4 * 4 + 2, cf * en.z);
                atomicAdd(fp + k4 * 4 + 3, cf * en.w);
            }
        }
    }
}

// ================= node finalize =================
__global__ void k_final(const float* __restrict__ h, const float* __restrict__ p,
                        const float* __restrict__ dv, const float* __restrict__ dt,
                        float* __restrict__ out) {
    int w = threadIdx.x >> 5, l = threadIdx.x & 31;
    int n = blockIdx.x * 8 + w;
    int ix = n * 32 + l;
    const float4* V1 = (const float4*)g_proj[0];
    const float4* V2 = (const float4*)g_proj[1];
    const float4* P3 = (const float4*)g_proj[4];
    const float4* D1 = (const float4*)g_proj[5];
    const float4* D2 = (const float4*)g_proj[6];
    const float4* TH = (const float4*)g_proj[7];
    const float4* FA = (const float4*)g_facc;

    float4 v1 = V1[ix], v2 = V2[ix], p3 = P3[ix], d1 = D1[ix], d2 = D2[ix];
    float4 th = TH[ix], fa = FA[ix];
    float cnt = (float)g_cnt0[n];

    float4 f;
    f.x = (d1.x - v1.x) * (cnt * relu_(th.x)) + fa.x;
    f.y = (d1.y - v1.y) * (cnt * relu_(th.y)) + fa.y;
    f.z = (d1.z - v1.z) * (cnt * relu_(th.z)) + fa.z;
    f.w = (d1.w - v1.w) * (cnt * relu_(th.w)) + fa.w;

    float sq = f.x * f.x + f.y * f.y + f.z * f.z + f.w * f.w;
#pragma unroll
    for (int off = 16; off > 0; off >>= 1) sq += __shfl_xor_sync(0xffffffffu, sq, off);
    float inv = 1.f / (sqrtf(sq) + 1e-9f);

    float dtv = dt[n];
    float dtp = dtv + 0.5f * dtv * dtv;

    float4 hv = ((const float4*)h)[ix];
    float4 pv = ((const float4*)p)[ix];
    float4 dvv = ((const float4*)dv)[ix];

    float4 ho, po, dq;
    ho.x = hv.x + lrelu(v2.x + f.x * dtv);
    ho.y = hv.y + lrelu(v2.y + f.y * dtv);
    ho.z = hv.z + lrelu(v2.z + f.z * dtv);
    ho.w = hv.w + lrelu(v2.w + f.w * dtv);
    po.x = pv.x + lrelu(p3.x + f.x * dtp);
    po.y = pv.y + lrelu(p3.y + f.y * dtp);
    po.z = pv.z + lrelu(p3.z + f.z * dtp);
    po.w = pv.w + lrelu(p3.w + f.w * dtp);
    dq.x = dvv.x + lrelu(d2.x + f.x * inv);
    dq.y = dvv.y + lrelu(d2.y + f.y * inv);
    dq.z = dvv.z + lrelu(d2.z + f.z * inv);
    dq.w = dvv.w + lrelu(d2.w + f.w * inv);

    float4* outH = (float4*)out;
    float4* outP = (float4*)(out + (size_t)NN * DD + (size_t)EE * DD);
    float4* outD = (float4*)(out + 2 * (size_t)NN * DD + (size_t)EE * DD);
    outH[ix] = ho;
    outP[ix] = po;
    outD[ix] = dq;
}

// ================= launch =================
extern "C" void kernel_launch(void* const* d_in, const int* in_sizes, int n_in,
                              void* d_out, int out_size) {
    const float* h   = (const float*)d_in[0];
    const float* e   = (const float*)d_in[1];
    const float* p   = (const float*)d_in[2];
    const float* dv  = (const float*)d_in[3];
    const float* dt  = (const float*)d_in[4];
    const int* smask = (const int*)d_in[5];
    const int* src   = (const int*)d_in[6];
    const int* dst   = (const int*)d_in[7];
    const float* W_V1 = (const float*)d_in[8],  *b_V1 = (const float*)d_in[9];
    const float* W_V2 = (const float*)d_in[10], *b_V2 = (const float*)d_in[11];
    const float* W_E1 = (const float*)d_in[12], *b_E1 = (const float*)d_in[13];
    const float* W_P1 = (const float*)d_in[14], *b_P1 = (const float*)d_in[15];
    const float* W_P2 = (const float*)d_in[16], *b_P2 = (const float*)d_in[17];
    const float* W_P3 = (const float*)d_in[18], *b_P3 = (const float*)d_in[19];
    const float* W_D1 = (const float*)d_in[20], *b_D1 = (const float*)d_in[21];
    const float* W_D2 = (const float*)d_in[22], *b_D2 = (const float*)d_in[23];
    const float* W_V  = (const float*)d_in[24], *b_V  = (const float*)d_in[25];
    const float* W_T  = (const float*)d_in[26], *b_T  = (const float*)d_in[27];
    float* out = (float*)d_out;

    cudaFuncSetAttribute(k_nodeg, cudaFuncAttributeMaxDynamicSharedMemorySize, SM_TOTAL);
    cudaFuncSetAttribute(k_edgeA, cudaFuncAttributeMaxDynamicSharedMemorySize, SM_TOTAL);
    cudaFuncSetAttribute(k_edgeB, cudaFuncAttributeMaxDynamicSharedMemorySize, SM_TOTAL);

    k_zero<<<640, 256>>>();
    k_wbf<<<88, 256>>>(W_V1, W_V2, W_P1, W_P2, W_P3, W_D1, W_D2, W_E1, W_V, W_T);
    k_count<<<EE / 256, 256>>>(smask, dst);
    k_nodeg<<<dim3((NN + 127) / 128, 8), 256, SM_TOTAL>>>(h, p, dv, b_V1, b_V2, b_P1,
                                                          b_P2, b_P3, b_D1, b_D2, b_T);
    k_edgeA<<<EE / 128, 256, SM_TOTAL>>>(e, src, dst, smask, b_E1, out + (size_t)NN * DD);
    k_edgeB<<<EE / 128, 256, SM_TOTAL>>>(h, b_V, src, dst);
    k_final<<<NN / 8, 256>>>(h, p, dv, dt, out);
}

// round 7
// speedup vs baseline: 1.1490x; 1.1490x over previous
#include <cuda_runtime.h>
#include <cuda_bf16.h>
#include <cstdint>
#include <math.h>

#define NN 10000
#define EE 320000
#define DD 128
#define NTILE_N 79      /* (NN+127)/128 */
#define NTILE_E 2500    /* EE/128 */
#define GRID_P 296      /* persistent grid: 148 SMs x 2 CTAs */

// ================= static device scratch =================
__device__ float g_proj[8][NN * DD];          // V1h V2h P1h P2h P3h D1h D2h Th
__device__ float g_enew[(size_t)EE * DD];
__device__ float g_facc[NN * DD];
__device__ int   g_cnt0[NN];
__device__ int   g_mlist[EE];
__device__ int   g_mcount;
// pre-split weight tiles in swizzled layout (32KB each):
// slots 0..6 node W (V1,V2,P1,P2,P3,D1,D2), 7 E1, 8 V, 9/10 = W_T halves
__device__ __align__(16) unsigned char g_wbh[11 * 32768];
__device__ __align__(16) unsigned char g_wbl[11 * 32768];

__device__ __forceinline__ float lrelu(float x) { return x > 0.f ? x : 0.01f * x; }
__device__ __forceinline__ float relu_(float x) { return x > 0.f ? x : 0.f; }

__device__ __forceinline__ uint32_t smem_u32(const void* p) {
    uint32_t a;
    asm("{ .reg .u64 t; cvta.to.shared.u64 t, %1; cvt.u32.u64 %0, t; }" : "=r"(a) : "l"(p));
    return a;
}
__device__ __forceinline__ uint32_t pack2(__nv_bfloat16 a, __nv_bfloat16 b) {
    __nv_bfloat162 t; t.x = a; t.y = b;
    return *reinterpret_cast<uint32_t*>(&t);
}

// swizzled byte offset inside a 128x128 bf16 tile (B tiles): row stride 256B
__device__ __forceinline__ uint32_t soff(int r, int c) {
    return (uint32_t)((r << 8) + ((((c >> 3) ^ (r & 7)) << 4) | ((c & 7) << 1)));
}
// swizzled byte offset inside a 128x64 bf16 tile (A half-tiles): row stride 128B
__device__ __forceinline__ uint32_t soff64(int r, int c) {
    return (uint32_t)((r << 7) + (((((c >> 3) ^ (r & 7)) & 7) << 4) | ((c & 7) << 1)));
}

__device__ __forceinline__ void ldsm4(uint32_t* r, uint32_t addr) {
    asm volatile("ldmatrix.sync.aligned.m8n8.x4.shared.b16 {%0,%1,%2,%3}, [%4];"
                 : "=r"(r[0]), "=r"(r[1]), "=r"(r[2]), "=r"(r[3]) : "r"(addr));
}
__device__ __forceinline__ void mma16816(float* d, const uint32_t* a,
                                         uint32_t b0, uint32_t b1) {
    asm volatile(
        "mma.sync.aligned.m16n8k16.row.col.f32.bf16.bf16.f32 "
        "{%0,%1,%2,%3}, {%4,%5,%6,%7}, {%8,%9}, {%0,%1,%2,%3};"
        : "+f"(d[0]), "+f"(d[1]), "+f"(d[2]), "+f"(d[3])
        : "r"(a[0]), "r"(a[1]), "r"(a[2]), "r"(a[3]), "r"(b0), "r"(b1));
}

// split 8 fp32 -> hi/lo bf16x2 quads
__device__ __forceinline__ void cvt8(float4 v0, float4 v1, uint4& hi, uint4& lo) {
    __nv_bfloat16 a0 = __float2bfloat16(v0.x), a1 = __float2bfloat16(v0.y);
    __nv_bfloat16 a2 = __float2bfloat16(v0.z), a3 = __float2bfloat16(v0.w);
    __nv_bfloat16 a4 = __float2bfloat16(v1.x), a5 = __float2bfloat16(v1.y);
    __nv_bfloat16 a6 = __float2bfloat16(v1.z), a7 = __float2bfloat16(v1.w);
    hi.x = pack2(a0, a1); hi.y = pack2(a2, a3);
    hi.z = pack2(a4, a5); hi.w = pack2(a6, a7);
    lo.x = pack2(__float2bfloat16(v0.x - __bfloat162float(a0)),
                 __float2bfloat16(v0.y - __bfloat162float(a1)));
    lo.y = pack2(__float2bfloat16(v0.z - __bfloat162float(a2)),
                 __float2bfloat16(v0.w - __bfloat162float(a3)));
    lo.z = pack2(__float2bfloat16(v1.x - __bfloat162float(a4)),
                 __float2bfloat16(v1.y - __bfloat162float(a5)));
    lo.w = pack2(__float2bfloat16(v1.z - __bfloat162float(a6)),
                 __float2bfloat16(v1.w - __bfloat162float(a7)));
}

// shared memory layout (102400 bytes -> 2 CTAs/SM)
#define SM_BIAS 0
#define SM_ROWA 512
#define SM_ROWB 1024
#define SM_ROWC 1536
#define SM_SV   2048
#define SM_AH   4096                 /* 128x64 bf16 hi (16KB) */
#define SM_AL   (4096 + 16384)       /* 128x64 bf16 lo (16KB) */
#define SM_BH   (4096 + 32768)       /* 128x128 bf16 hi (32KB) RESIDENT */
#define SM_BL   (4096 + 65536)       /* 128x128 bf16 lo (32KB) RESIDENT */
#define SM_C    4096                 /* fp32 C 64rows x 512B, overlays A only */
#define SM_TOTAL (4096 + 98304)

// C chunk-swizzled offset: local row r (0..63), float4-chunk c4 (0..31)
__device__ __forceinline__ uint32_t coff(int r, int c4) {
    return (uint32_t)(SM_C + r * 512 + (((c4 ^ (r & 7)) & 31) << 4));
}

// ---- 3-term split GEMM over one K-half, warp tile 32(M) x 64(N), 8 warps ----
__device__ __forceinline__ void gemm_half(uint32_t smb, int lane, int wm, int wn,
                                          int kh, float (&acc)[2][8][4]) {
    const int fr = lane & 15;
    const int fc = (lane >> 4) << 3;
    const int m0 = wm * 32;
    const int n0 = wn * 64;
#pragma unroll
    for (int ks = 0; ks < 4; ks++) {
        uint32_t aH[2][4], aL[2][4];
#pragma unroll
        for (int mf = 0; mf < 2; mf++) {
            ldsm4(aH[mf], smb + SM_AH + soff64(m0 + mf * 16 + fr, ks * 16 + fc));
            ldsm4(aL[mf], smb + SM_AL + soff64(m0 + mf * 16 + fr, ks * 16 + fc));
        }
        const int kc = kh * 64 + ks * 16 + fc;
#pragma unroll
        for (int bn = 0; bn < 4; bn++) {
            uint32_t bH[4], bL[4];
            ldsm4(bH, smb + SM_BH + soff(n0 + bn * 16 + fr, kc));
            ldsm4(bL, smb + SM_BL + soff(n0 + bn * 16 + fr, kc));
#pragma unroll
            for (int mf = 0; mf < 2; mf++) {
                mma16816(acc[mf][2 * bn],     aH[mf], bH[0], bH[2]);
                mma16816(acc[mf][2 * bn + 1], aH[mf], bH[1], bH[3]);
                mma16816(acc[mf][2 * bn],     aL[mf], bH[0], bH[2]);
                mma16816(acc[mf][2 * bn + 1], aL[mf], bH[1], bH[3]);
                mma16816(acc[mf][2 * bn],     aH[mf], bL[0], bL[2]);
                mma16816(acc[mf][2 * bn + 1], aH[mf], bL[1], bL[3]);
            }
        }
    }
}

__device__ __forceinline__ void copy_B(char* sm, int slot, int tid) {
    const uint4* gh = (const uint4*)(g_wbh + slot * 32768);
    const uint4* gl = (const uint4*)(g_wbl + slot * 32768);
    uint4* bh = (uint4*)(sm + SM_BH);
    uint4* bl = (uint4*)(sm + SM_BL);
    for (int i = tid; i < 2048; i += 256) { bh[i] = gh[i]; bl[i] = gl[i]; }
}

// store prefetched regs (one K-half of A) into swizzled smem
__device__ __forceinline__ void stage_sts(char* sm, int tid, const float4 (&s)[4][2]) {
#pragma unroll
    for (int i = 0; i < 4; i++) {
        int u = tid + i * 256;
        int row = u >> 3, ch = u & 7;
        uint4 hi, lo; cvt8(s[i][0], s[i][1], hi, lo);
        uint32_t off = soff64(row, ch * 8);
        *(uint4*)(sm + SM_AH + off) = hi;
        *(uint4*)(sm + SM_AL + off) = lo;
    }
}

// ================= prep kernels =================
__global__ void k_zero() {
    int i = blockIdx.x * blockDim.x + threadIdx.x;
    int stride = gridDim.x * blockDim.x;
    for (int t = i; t < NN * DD; t += stride) g_facc[t] = 0.f;
    for (int t = i; t < NN; t += stride) g_cnt0[t] = 0;
    if (i == 0) g_mcount = 0;
}

__global__ void k_wbf(const float* W0, const float* W1, const float* W2, const float* W3,
                      const float* W4, const float* W5, const float* W6, const float* W7,
                      const float* W8, const float* WT) {
    const float* Wp[9] = {W0, W1, W2, W3, W4, W5, W6, W7, W8};
    int i = blockIdx.x * blockDim.x + threadIdx.x;
    int stride = gridDim.x * blockDim.x;
    for (int t = i; t < 11 * 2048; t += stride) {
        int slot = t >> 11, r = t & 2047;
        int n = r >> 4, k8 = r & 15;
        const float* srcp;
        if (slot < 9) srcp = Wp[slot] + n * 128 + k8 * 8;
        else if (slot == 9) srcp = WT + n * 256 + k8 * 8;
        else srcp = WT + n * 256 + 128 + k8 * 8;
        float4 v0 = ((const float4*)srcp)[0];
        float4 v1 = ((const float4*)srcp)[1];
        uint4 hi, lo; cvt8(v0, v1, hi, lo);
        uint32_t off = (uint32_t)slot * 32768u + soff(n, k8 * 8);
        *reinterpret_cast<uint4*>(g_wbh + off) = hi;
        *reinterpret_cast<uint4*>(g_wbl + off) = lo;
    }
}

__global__ void k_count(const int* __restrict__ smask, const int* __restrict__ dst) {
    int e = blockIdx.x * 256 + threadIdx.x;
    int lane = threadIdx.x & 31;
    int sm_ = smask[e];
    int d_ = dst[e];
    unsigned bal = __ballot_sync(0xffffffffu, sm_ == 1);
    if (sm_ == 0) atomicAdd(&g_cnt0[d_], 1);
    int lead = bal ? (__ffs(bal) - 1) : 0;
    int basec = 0;
    if (bal && lane == lead) basec = atomicAdd(&g_mcount, __popc(bal));
    basec = __shfl_sync(0xffffffffu, basec, lead);
    if (sm_ == 1) g_mlist[basec + __popc(bal & ((1u << lane) - 1u))] = e;
}

// ================= node GEMMs: persistent, pair = blockIdx.x & 7 =================
__global__ void __launch_bounds__(256, 2)
k_nodeg(const float* __restrict__ h, const float* __restrict__ p,
        const float* __restrict__ dv,
        const float* bV1, const float* bV2, const float* bP1,
        const float* bP2, const float* bP3, const float* bD1,
        const float* bD2, const float* bT) {
    extern __shared__ char sm[];
    uint32_t smb = smem_u32(sm);
    int tid = threadIdx.x, lane = tid & 31, wid = tid >> 5;
    int wm = wid & 3, wn = wid >> 2;
    int pair = blockIdx.x & 7;
    int cstep = gridDim.x >> 3;

    const float* X0;
    const float* bias;
    int slot0;
    switch (pair) {
        case 0: X0 = h;  slot0 = 0; bias = bV1; break;
        case 1: X0 = h;  slot0 = 1; bias = bV2; break;
        case 2: X0 = p;  slot0 = 2; bias = bP1; break;
        case 3: X0 = p;  slot0 = 3; bias = bP2; break;
        case 4: X0 = p;  slot0 = 4; bias = bP3; break;
        case 5: X0 = dv; slot0 = 5; bias = bD1; break;
        case 6: X0 = dv; slot0 = 6; bias = bD2; break;
        default: X0 = h; slot0 = 9; bias = bT; break;
    }
    if (tid < 128) ((float*)(sm + SM_BIAS))[tid] = bias[tid];
    if (pair != 7) copy_B(sm, slot0, tid);
    int nph = (pair == 7) ? 2 : 1;
    float* outp = g_proj[pair];
    int q = lane >> 2, m = lane & 3;

    for (int t = blockIdx.x >> 3; t < NTILE_N; t += cstep) {
        int r0 = t * 128;
        __syncthreads();

        float acc[2][8][4];
#pragma unroll
        for (int mf = 0; mf < 2; mf++)
#pragma unroll
            for (int j = 0; j < 8; j++)
#pragma unroll
                for (int i = 0; i < 4; i++) acc[mf][j][i] = 0.f;

        for (int ph = 0; ph < nph; ph++) {
            const float* X = (pair == 7 && ph == 1) ? dv : X0;
            if (pair == 7) { copy_B(sm, slot0 + ph, tid); }
            float4 s[4][2];
#pragma unroll
            for (int i = 0; i < 4; i++) {
                int u = tid + i * 256;
                int row = u >> 3, ch = u & 7;
                int g = r0 + row;
                s[i][0] = make_float4(0.f, 0.f, 0.f, 0.f);
                s[i][1] = s[i][0];
                if (g < NN) {
                    s[i][0] = ((const float4*)X)[(size_t)g * 32 + ch * 2];
                    s[i][1] = ((const float4*)X)[(size_t)g * 32 + ch * 2 + 1];
                }
            }
            stage_sts(sm, tid, s);
            __syncthreads();
            // prefetch kh1 while gemm kh0 runs
#pragma unroll
            for (int i = 0; i < 4; i++) {
                int u = tid + i * 256;
                int row = u >> 3, ch = u & 7;
                int g = r0 + row;
                if (g < NN) {
                    s[i][0] = ((const float4*)X)[(size_t)g * 32 + 16 + ch * 2];
                    s[i][1] = ((const float4*)X)[(size_t)g * 32 + 16 + ch * 2 + 1];
                } else {
                    s[i][0] = make_float4(0.f, 0.f, 0.f, 0.f);
                    s[i][1] = s[i][0];
                }
            }
            gemm_half(smb, lane, wm, wn, 0, acc);
            __syncthreads();
            stage_sts(sm, tid, s);
            __syncthreads();
            gemm_half(smb, lane, wm, wn, 1, acc);
            if (pair == 7 && ph == 0) __syncthreads();  // before B reload
        }

        // register epilogue (R6-proven for nodeg)
        const float* bias_s = (const float*)(sm + SM_BIAS);
#pragma unroll
        for (int mf = 0; mf < 2; mf++) {
            int r1 = r0 + wm * 32 + mf * 16 + q;
            int r2 = r1 + 8;
#pragma unroll
            for (int j = 0; j < 8; j++) {
                int col = wn * 64 + j * 8 + m * 2;
                float b0 = bias_s[col], b1 = bias_s[col + 1];
                if (r1 < NN)
                    *(float2*)&outp[(size_t)r1 * DD + col] =
                        make_float2(acc[mf][j][0] + b0, acc[mf][j][1] + b1);
                if (r2 < NN)
                    *(float2*)&outp[(size_t)r2 * DD + col] =
                        make_float2(acc[mf][j][2] + b0, acc[mf][j][3] + b1);
            }
        }
    }
}

// ================= edge pass A: persistent, resident B, smem-C epilogue ==========
__global__ void __launch_bounds__(256, 2)
k_edgeA(const float* __restrict__ e_in, const int* __restrict__ src,
        const int* __restrict__ dst, const int* __restrict__ smask,
        const float* __restrict__ bE1, float* __restrict__ e_out) {
    extern __shared__ char sm[];
    uint32_t smb = smem_u32(sm);
    int tid = threadIdx.x, lane = tid & 31, wid = tid >> 5;
    int wm = wid & 3, wn = wid >> 2;
    int q = lane >> 2, m = lane & 3;

    if (tid < 128) ((float*)(sm + SM_BIAS))[tid] = bE1[tid];
    copy_B(sm, 7, tid);
    const float* P1 = g_proj[2];
    const float* P2 = g_proj[3];

    for (int t = blockIdx.x; t < NTILE_E; t += gridDim.x) {
        int e0 = t * 128;
        __syncthreads();
        if (tid < 128) {
            int eg = e0 + tid;
            ((int*)(sm + SM_ROWA))[tid] = src[eg];
            ((int*)(sm + SM_ROWB))[tid] = dst[eg];
            ((int*)(sm + SM_ROWC))[tid] = smask[eg];
        }
        float4 s[4][2];
#pragma unroll
        for (int i = 0; i < 4; i++) {
            int u = tid + i * 256;
            int row = u >> 3, ch = u & 7;
            s[i][0] = ((const float4*)e_in)[(size_t)(e0 + row) * 32 + ch * 2];
            s[i][1] = ((const float4*)e_in)[(size_t)(e0 + row) * 32 + ch * 2 + 1];
        }
        stage_sts(sm, tid, s);
        __syncthreads();

        float acc[2][8][4];
#pragma unroll
        for (int mf = 0; mf < 2; mf++)
#pragma unroll
            for (int j = 0; j < 8; j++)
#pragma unroll
                for (int i = 0; i < 4; i++) acc[mf][j][i] = 0.f;

        // prefetch kh1 while gemm kh0 runs
#pragma unroll
        for (int i = 0; i < 4; i++) {
            int u = tid + i * 256;
            int row = u >> 3, ch = u & 7;
            s[i][0] = ((const float4*)e_in)[(size_t)(e0 + row) * 32 + 16 + ch * 2];
            s[i][1] = ((const float4*)e_in)[(size_t)(e0 + row) * 32 + 16 + ch * 2 + 1];
        }
        gemm_half(smb, lane, wm, wn, 0, acc);
        __syncthreads();
        stage_sts(sm, tid, s);
        __syncthreads();
        gemm_half(smb, lane, wm, wn, 1, acc);

        // epilogue: 2 passes of 64 rows through swizzled C in the A region
        const float* bias_s = (const float*)(sm + SM_BIAS);
        const int* ssrc = (const int*)(sm + SM_ROWA);
        const int* sdst = (const int*)(sm + SM_ROWB);
        const int* smsk = (const int*)(sm + SM_ROWC);
#pragma unroll
        for (int ph = 0; ph < 2; ph++) {
            __syncthreads();
            if ((wm >> 1) == ph) {
                int wml = wm & 1;
#pragma unroll
                for (int mf = 0; mf < 2; mf++) {
                    int rb = wml * 32 + mf * 16 + q;  // local row 0..63
#pragma unroll
                    for (int j = 0; j < 8; j++) {
                        int col = wn * 64 + j * 8 + m * 2;
                        int c4 = col >> 2;
                        uint32_t inoff = (uint32_t)((m & 1) * 8);
                        *(float2*)(sm + coff(rb, c4) + inoff) =
                            make_float2(acc[mf][j][0], acc[mf][j][1]);
                        *(float2*)(sm + coff(rb + 8, c4) + inoff) =
                            make_float2(acc[mf][j][2], acc[mf][j][3]);
                    }
                }
            }
            __syncthreads();
            for (int u = tid; u < 2048; u += 256) {
                int r = u >> 5, c4 = u & 31;
                int lr = ph * 64 + r;
                int eg = e0 + lr;
                int si = ssrc[lr], di = sdst[lr], msk = smsk[lr];
                float4 cC = *(float4*)(sm + coff(r, c4));
                float4 bv = *(const float4*)&bias_s[c4 * 4];
                float4 p1 = *(const float4*)&P1[(size_t)di * DD + c4 * 4];
                float4 p2 = *(const float4*)&P2[(size_t)si * DD + c4 * 4];
                float4 ev = *(const float4*)&e_in[(size_t)eg * DD + c4 * 4];
                float4 en;
                en.x = 0.5f * (p1.x - p2.x + cC.x + bv.x);
                en.y = 0.5f * (p1.y - p2.y + cC.y + bv.y);
                en.z = 0.5f * (p1.z - p2.z + cC.z + bv.z);
                en.w = 0.5f * (p1.w - p2.w + cC.w + bv.w);
                float4 o;
                o.x = ev.x + lrelu(en.x);
                o.y = ev.y + lrelu(en.y);
                o.z = ev.z + lrelu(en.z);
                o.w = ev.w + lrelu(en.w);
                *(float4*)&e_out[(size_t)eg * DD + c4 * 4] = o;
                if (msk) *(float4*)&g_enew[(size_t)eg * DD + c4 * 4] = en;
            }
        }
    }
}

// ================= edge pass B: persistent, resident B, masked V GEMM =============
__global__ void __launch_bounds__(256, 2)
k_edgeB(const float* __restrict__ h, const float* __restrict__ bV,
        const int* __restrict__ src, const int* __restrict__ dst) {
    extern __shared__ char sm[];
    uint32_t smb = smem_u32(sm);
    int tid = threadIdx.x, lane = tid & 31, wid = tid >> 5;
    int wm = wid & 3, wn = wid >> 2;
    int q = lane >> 2, m = lane & 3;
    int mc = g_mcount;
    int ntiles = (mc + 127) >> 7;

    if (tid < 128) ((float*)(sm + SM_BIAS))[tid] = bV[tid];
    copy_B(sm, 8, tid);
    int* seid = (int*)(sm + SM_ROWC);
    int* ssrc = (int*)(sm + SM_ROWA);
    int* sdst = (int*)(sm + SM_ROWB);
    const float* bias_s = (const float*)(sm + SM_BIAS);
    float* svb = (float*)(sm + SM_SV);

    for (int t = blockIdx.x; t < ntiles; t += gridDim.x) {
        int base = t * 128;
        int nt = min(128, mc - base);
        __syncthreads();
        if (tid < 128) {
            int eid = (tid < nt) ? g_mlist[base + tid] : -1;
            seid[tid] = eid;
            ssrc[tid] = (eid >= 0) ? src[eid] : 0;
            sdst[tid] = (eid >= 0) ? dst[eid] : 0;
        }
        __syncthreads();

        float acc[2][8][4];
#pragma unroll
        for (int mf = 0; mf < 2; mf++)
#pragma unroll
            for (int j = 0; j < 8; j++)
#pragma unroll
                for (int i = 0; i < 4; i++) acc[mf][j][i] = 0.f;

        for (int kh = 0; kh < 2; kh++) {
            for (int u = tid; u < 1024; u += 256) {
                int row = u >> 3, ch = u & 7;
                float4 v0 = make_float4(0.f, 0.f, 0.f, 0.f), v1 = v0;
                if (row < nt) {
                    float4 hs0 = ((const float4*)h)[(size_t)ssrc[row] * 32 + kh * 16 + ch * 2];
                    float4 hs1 = ((const float4*)h)[(size_t)ssrc[row] * 32 + kh * 16 + ch * 2 + 1];
                    float4 hd0 = ((const float4*)h)[(size_t)sdst[row] * 32 + kh * 16 + ch * 2];
                    float4 hd1 = ((const float4*)h)[(size_t)sdst[row] * 32 + kh * 16 + ch * 2 + 1];
                    v0.x = hs0.x * hd0.x; v0.y = hs0.y * hd0.y;
                    v0.z = hs0.z * hd0.z; v0.w = hs0.w * hd0.w;
                    v1.x = hs1.x * hd1.x; v1.y = hs1.y * hd1.y;
                    v1.z = hs1.z * hd1.z; v1.w = hs1.w * hd1.w;
                }
                uint4 hi, lo; cvt8(v0, v1, hi, lo);
                uint32_t off = soff64(row, ch * 8);
                *(uint4*)(sm + SM_AH + off) = hi;
                *(uint4*)(sm + SM_AL + off) = lo;
            }
            __syncthreads();
            gemm_half(smb, lane, wm, wn, kh, acc);
            __syncthreads();
        }

        float s0[2] = {0.f, 0.f}, s1[2] = {0.f, 0.f};
#pragma unroll
        for (int mf = 0; mf < 2; mf++)
#pragma unroll
            for (int j = 0; j < 8; j++) {
                float b0 = bias_s[wn * 64 + j * 8 + m * 2];
                float b1 = bias_s[wn * 64 + j * 8 + m * 2 + 1];
                s0[mf] += relu_(acc[mf][j][0] + b0) + relu_(acc[mf][j][1] + b1);
                s1[mf] += relu_(acc[mf][j][2] + b0) + relu_(acc[mf][j][3] + b1);
            }
#pragma unroll
        for (int mf = 0; mf < 2; mf++) {
            s0[mf] += __shfl_xor_sync(0xffffffffu, s0[mf], 1);
            s0[mf] += __shfl_xor_sync(0xffffffffu, s0[mf], 2);
            s1[mf] += __shfl_xor_sync(0xffffffffu, s1[mf], 1);
            s1[mf] += __shfl_xor_sync(0xffffffffu, s1[mf], 2);
        }
        if (m == 0) {
#pragma unroll
            for (int mf = 0; mf < 2; mf++) {
                svb[wn * 128 + wm * 32 + mf * 16 + q] = s0[mf];
                svb[wn * 128 + wm * 32 + mf * 16 + q + 8] = s1[mf];
            }
        }
        __syncthreads();

        if (tid < nt) {
            float sv = svb[tid] + svb[128 + tid];
            int eid = seid[tid];
            const float4* EN = (const float4*)g_enew + (size_t)eid * 32;
            float sq = 0.f;
#pragma unroll 8
            for (int k4 = 0; k4 < 32; k4++) {
                float4 en = EN[k4];
                sq += en.x * en.x + en.y * en.y + en.z * en.z + en.w * en.w;
            }
            float L = sqrtf(sq);
            if (L > 1e-9f && sv > 0.f) {
                float r = 0.5f * sqrtf(L);
                float cf = sv * expf(-r / 0.3f) / (1.2f * L * sqrtf(L));
                float* fp = &g_facc[(size_t)sdst[tid] * DD];
#pragma unroll 8
                for (int k4 = 0; k4 < 32; k4++) {
                    float4 en = EN[k4];
                    atomicAdd(fp + k4 * 4 + 0, cf * en.x);
                    atomicAdd(fp + k4 * 4 + 1, cf * en.y);
                    atomicAdd(fp + k4 * 4 + 2, cf * en.z);
                    atomicAdd(fp + k4 * 4 + 3, cf * en.w);
                }
            }
        }
    }
}

// ================= node finalize =================
__global__ void k_final(const float* __restrict__ h, const float* __restrict__ p,
                        const float* __restrict__ dv, const float* __restrict__ dt,
                        float* __restrict__ out) {
    int w = threadIdx.x >> 5, l = threadIdx.x & 31;
    int n = blockIdx.x * 8 + w;
    int ix = n * 32 + l;
    const float4* V1 = (const float4*)g_proj[0];
    const float4* V2 = (const float4*)g_proj[1];
    const float4* P3 = (const float4*)g_proj[4];
    const float4* D1 = (const float4*)g_proj[5];
    const float4* D2 = (const float4*)g_proj[6];
    const float4* TH = (const float4*)g_proj[7];
    const float4* FA = (const float4*)g_facc;

    float4 v1 = V1[ix], v2 = V2[ix], p3 = P3[ix], d1 = D1[ix], d2 = D2[ix];
    float4 th = TH[ix], fa = FA[ix];
    float cnt = (float)g_cnt0[n];

    float4 f;
    f.x = (d1.x - v1.x) * (cnt * relu_(th.x)) + fa.x;
    f.y = (d1.y - v1.y) * (cnt * relu_(th.y)) + fa.y;
    f.z = (d1.z - v1.z) * (cnt * relu_(th.z)) + fa.z;
    f.w = (d1.w - v1.w) * (cnt * relu_(th.w)) + fa.w;

    float sq = f.x * f.x + f.y * f.y + f.z * f.z + f.w * f.w;
#pragma unroll
    for (int off = 16; off > 0; off >>= 1) sq += __shfl_xor_sync(0xffffffffu, sq, off);
    float inv = 1.f / (sqrtf(sq) + 1e-9f);

    float dtv = dt[n];
    float dtp = dtv + 0.5f * dtv * dtv;

    float4 hv = ((const float4*)h)[ix];
    float4 pv = ((const float4*)p)[ix];
    float4 dvv = ((const float4*)dv)[ix];

    float4 ho, po, dq;
    ho.x = hv.x + lrelu(v2.x + f.x * dtv);
    ho.y = hv.y + lrelu(v2.y + f.y * dtv);
    ho.z = hv.z + lrelu(v2.z + f.z * dtv);
    ho.w = hv.w + lrelu(v2.w + f.w * dtv);
    po.x = pv.x + lrelu(p3.x + f.x * dtp);
    po.y = pv.y + lrelu(p3.y + f.y * dtp);
    po.z = pv.z + lrelu(p3.z + f.z * dtp);
    po.w = pv.w + lrelu(p3.w + f.w * dtp);
    dq.x = dvv.x + lrelu(d2.x + f.x * inv);
    dq.y = dvv.y + lrelu(d2.y + f.y * inv);
    dq.z = dvv.z + lrelu(d2.z + f.z * inv);
    dq.w = dvv.w + lrelu(d2.w + f.w * inv);

    float4* outH = (float4*)out;
    float4* outP = (float4*)(out + (size_t)NN * DD + (size_t)EE * DD);
    float4* outD = (float4*)(out + 2 * (size_t)NN * DD + (size_t)EE * DD);
    outH[ix] = ho;
    outP[ix] = po;
    outD[ix] = dq;
}

// ================= launch =================
extern "C" void kernel_launch(void* const* d_in, const int* in_sizes, int n_in,
                              void* d_out, int out_size) {
    const float* h   = (const float*)d_in[0];
    const float* e   = (const float*)d_in[1];
    const float* p   = (const float*)d_in[2];
    const float* dv  = (const float*)d_in[3];
    const float* dt  = (const float*)d_in[4];
    const int* smask = (const int*)d_in[5];
    const int* src   = (const int*)d_in[6];
    const int* dst   = (const int*)d_in[7];
    const float* W_V1 = (const float*)d_in[8],  *b_V1 = (const float*)d_in[9];
    const float* W_V2 = (const float*)d_in[10], *b_V2 = (const float*)d_in[11];
    const float* W_E1 = (const float*)d_in[12], *b_E1 = (const float*)d_in[13];
    const float* W_P1 = (const float*)d_in[14], *b_P1 = (const float*)d_in[15];
    const float* W_P2 = (const float*)d_in[16], *b_P2 = (const float*)d_in[17];
    const float* W_P3 = (const float*)d_in[18], *b_P3 = (const float*)d_in[19];
    const float* W_D1 = (const float*)d_in[20], *b_D1 = (const float*)d_in[21];
    const float* W_D2 = (const float*)d_in[22], *b_D2 = (const float*)d_in[23];
    const float* W_V  = (const float*)d_in[24], *b_V  = (const float*)d_in[25];
    const float* W_T  = (const float*)d_in[26], *b_T  = (const float*)d_in[27];
    float* out = (float*)d_out;

    cudaFuncSetAttribute(k_nodeg, cudaFuncAttributeMaxDynamicSharedMemorySize, SM_TOTAL);
    cudaFuncSetAttribute(k_edgeA, cudaFuncAttributeMaxDynamicSharedMemorySize, SM_TOTAL);
    cudaFuncSetAttribute(k_edgeB, cudaFuncAttributeMaxDynamicSharedMemorySize, SM_TOTAL);

    k_zero<<<640, 256>>>();
    k_wbf<<<88, 256>>>(W_V1, W_V2, W_P1, W_P2, W_P3, W_D1, W_D2, W_E1, W_V, W_T);
    k_count<<<EE / 256, 256>>>(smask, dst);
    k_nodeg<<<GRID_P, 256, SM_TOTAL>>>(h, p, dv, b_V1, b_V2, b_P1, b_P2, b_P3,
                                       b_D1, b_D2, b_T);
    k_edgeA<<<GRID_P, 256, SM_TOTAL>>>(e, src, dst, smask, b_E1, out + (size_t)NN * DD);
    k_edgeB<<<GRID_P, 256, SM_TOTAL>>>(h, b_V, src, dst);
    k_final<<<NN / 8, 256>>>(h, p, dv, dt, out);
}

// round 8
// speedup vs baseline: 1.4391x; 1.2525x over previous
#include <cuda_runtime.h>
#include <cuda_bf16.h>
#include <cstdint>
#include <math.h>

#define NN 10000
#define EE 320000
#define DD 128
#define NTILE_N 79      /* (NN+127)/128 */
#define NTILE_E 2500    /* EE/128 */
#define GRID_P 296      /* persistent grid: 148 SMs x 2 CTAs */

// ================= static device scratch =================
__device__ float g_proj[9][NN * DD];     // V1h V2h P1h P2h P3h D1h D2h ThA ThB
__device__ float g_enew[(size_t)EE * DD];
__device__ float g_enorm[EE];
__device__ float g_facc[NN * DD];
__device__ int   g_cnt0[NN];
__device__ int   g_mlist[EE];
__device__ int   g_mcount;
__device__ float g_bzero[DD];            // stays zero (module-load init)
// pre-split weight tiles in swizzled layout (32KB each):
// slots 0..6 node W (V1,V2,P1,P2,P3,D1,D2), 7 E1, 8 V, 9/10 = W_T halves
__device__ __align__(16) unsigned char g_wbh[11 * 32768];
__device__ __align__(16) unsigned char g_wbl[11 * 32768];

__device__ __forceinline__ float lrelu(float x) { return x > 0.f ? x : 0.01f * x; }
__device__ __forceinline__ float relu_(float x) { return x > 0.f ? x : 0.f; }

__device__ __forceinline__ uint32_t smem_u32(const void* p) {
    uint32_t a;
    asm("{ .reg .u64 t; cvta.to.shared.u64 t, %1; cvt.u32.u64 %0, t; }" : "=r"(a) : "l"(p));
    return a;
}
__device__ __forceinline__ uint32_t pack2(__nv_bfloat16 a, __nv_bfloat16 b) {
    __nv_bfloat162 t; t.x = a; t.y = b;
    return *reinterpret_cast<uint32_t*>(&t);
}

// swizzled byte offset inside a 128x128 bf16 tile (B tiles): row stride 256B
__device__ __forceinline__ uint32_t soff(int r, int c) {
    return (uint32_t)((r << 8) + ((((c >> 3) ^ (r & 7)) << 4) | ((c & 7) << 1)));
}
// swizzled byte offset inside a 128x64 bf16 tile (A half-tiles): row stride 128B
__device__ __forceinline__ uint32_t soff64(int r, int c) {
    return (uint32_t)((r << 7) + (((((c >> 3) ^ (r & 7)) & 7) << 4) | ((c & 7) << 1)));
}

__device__ __forceinline__ void ldsm4(uint32_t* r, uint32_t addr) {
    asm volatile("ldmatrix.sync.aligned.m8n8.x4.shared.b16 {%0,%1,%2,%3}, [%4];"
                 : "=r"(r[0]), "=r"(r[1]), "=r"(r[2]), "=r"(r[3]) : "r"(addr));
}
__device__ __forceinline__ void mma16816(float* d, const uint32_t* a,
                                         uint32_t b0, uint32_t b1) {
    asm volatile(
        "mma.sync.aligned.m16n8k16.row.col.f32.bf16.bf16.f32 "
        "{%0,%1,%2,%3}, {%4,%5,%6,%7}, {%8,%9}, {%0,%1,%2,%3};"
        : "+f"(d[0]), "+f"(d[1]), "+f"(d[2]), "+f"(d[3])
        : "r"(a[0]), "r"(a[1]), "r"(a[2]), "r"(a[3]), "r"(b0), "r"(b1));
}

// split 8 fp32 -> hi/lo bf16x2 quads
__device__ __forceinline__ void cvt8(float4 v0, float4 v1, uint4& hi, uint4& lo) {
    __nv_bfloat16 a0 = __float2bfloat16(v0.x), a1 = __float2bfloat16(v0.y);
    __nv_bfloat16 a2 = __float2bfloat16(v0.z), a3 = __float2bfloat16(v0.w);
    __nv_bfloat16 a4 = __float2bfloat16(v1.x), a5 = __float2bfloat16(v1.y);
    __nv_bfloat16 a6 = __float2bfloat16(v1.z), a7 = __float2bfloat16(v1.w);
    hi.x = pack2(a0, a1); hi.y = pack2(a2, a3);
    hi.z = pack2(a4, a5); hi.w = pack2(a6, a7);
    lo.x = pack2(__float2bfloat16(v0.x - __bfloat162float(a0)),
                 __float2bfloat16(v0.y - __bfloat162float(a1)));
    lo.y = pack2(__float2bfloat16(v0.z - __bfloat162float(a2)),
                 __float2bfloat16(v0.w - __bfloat162float(a3)));
    lo.z = pack2(__float2bfloat16(v1.x - __bfloat162float(a4)),
                 __float2bfloat16(v1.y - __bfloat162float(a5)));
    lo.w = pack2(__float2bfloat16(v1.z - __bfloat162float(a6)),
                 __float2bfloat16(v1.w - __bfloat162float(a7)));
}

// shared memory layout (102400 bytes -> 2 CTAs/SM)
#define SM_BIAS 0
#define SM_ROWA 512
#define SM_ROWB 1024
#define SM_ROWC 1536
#define SM_SV   2048
#define SM_AH   4096                 /* 128x64 bf16 hi (16KB) */
#define SM_AL   (4096 + 16384)       /* 128x64 bf16 lo (16KB) */
#define SM_BH   (4096 + 32768)       /* 128x128 bf16 hi (32KB) RESIDENT */
#define SM_BL   (4096 + 65536)       /* 128x128 bf16 lo (32KB) RESIDENT */
#define SM_C    4096                 /* fp32 C 64rows x 512B, overlays A only */
#define SM_TOTAL (4096 + 98304)

// C chunk-swizzled offset: local row r (0..63), float4-chunk c4 (0..31)
__device__ __forceinline__ uint32_t coff(int r, int c4) {
    return (uint32_t)(SM_C + r * 512 + (((c4 ^ (r & 7)) & 31) << 4));
}

// ---- 3-term split GEMM over one K-half, warp tile 32(M) x 64(N), 8 warps ----
__device__ __forceinline__ void gemm_half(uint32_t smb, int lane, int wm, int wn,
                                          int kh, float (&acc)[2][8][4]) {
    const int fr = lane & 15;
    const int fc = (lane >> 4) << 3;
    const int m0 = wm * 32;
    const int n0 = wn * 64;
#pragma unroll
    for (int ks = 0; ks < 4; ks++) {
        uint32_t aH[2][4], aL[2][4];
#pragma unroll
        for (int mf = 0; mf < 2; mf++) {
            ldsm4(aH[mf], smb + SM_AH + soff64(m0 + mf * 16 + fr, ks * 16 + fc));
            ldsm4(aL[mf], smb + SM_AL + soff64(m0 + mf * 16 + fr, ks * 16 + fc));
        }
        const int kc = kh * 64 + ks * 16 + fc;
#pragma unroll
        for (int bn = 0; bn < 4; bn++) {
            uint32_t bH[4], bL[4];
            ldsm4(bH, smb + SM_BH + soff(n0 + bn * 16 + fr, kc));
            ldsm4(bL, smb + SM_BL + soff(n0 + bn * 16 + fr, kc));
#pragma unroll
            for (int mf = 0; mf < 2; mf++) {
                mma16816(acc[mf][2 * bn],     aH[mf], bH[0], bH[2]);
                mma16816(acc[mf][2 * bn + 1], aH[mf], bH[1], bH[3]);
                mma16816(acc[mf][2 * bn],     aL[mf], bH[0], bH[2]);
                mma16816(acc[mf][2 * bn + 1], aL[mf], bH[1], bH[3]);
                mma16816(acc[mf][2 * bn],     aH[mf], bL[0], bL[2]);
                mma16816(acc[mf][2 * bn + 1], aH[mf], bL[1], bL[3]);
            }
        }
    }
}

__device__ __forceinline__ void copy_B(char* sm, int slot, int tid) {
    const uint4* gh = (const uint4*)(g_wbh + slot * 32768);
    const uint4* gl = (const uint4*)(g_wbl + slot * 32768);
    uint4* bh = (uint4*)(sm + SM_BH);
    uint4* bl = (uint4*)(sm + SM_BL);
    for (int i = tid; i < 2048; i += 256) { bh[i] = gh[i]; bl[i] = gl[i]; }
}

// store prefetched regs (one K-half of A) into swizzled smem
__device__ __forceinline__ void stage_sts(char* sm, int tid, const float4 (&s)[4][2]) {
#pragma unroll
    for (int i = 0; i < 4; i++) {
        int u = tid + i * 256;
        int row = u >> 3, ch = u & 7;
        uint4 hi, lo; cvt8(s[i][0], s[i][1], hi, lo);
        uint32_t off = soff64(row, ch * 8);
        *(uint4*)(sm + SM_AH + off) = hi;
        *(uint4*)(sm + SM_AL + off) = lo;
    }
}

// ================= prep: zero scratch + weight split/swizzle =================
__global__ void k_prep(const float* W0, const float* W1, const float* W2, const float* W3,
                       const float* W4, const float* W5, const float* W6, const float* W7,
                       const float* W8, const float* WT) {
    const float* Wp[9] = {W0, W1, W2, W3, W4, W5, W6, W7, W8};
    int i = blockIdx.x * blockDim.x + threadIdx.x;
    int stride = gridDim.x * blockDim.x;
    for (int t = i; t < NN * DD; t += stride) g_facc[t] = 0.f;
    for (int t = i; t < NN; t += stride) g_cnt0[t] = 0;
    if (i == 0) g_mcount = 0;
    for (int t = i; t < 11 * 2048; t += stride) {
        int slot = t >> 11, r = t & 2047;
        int n = r >> 4, k8 = r & 15;
        const float* srcp;
        if (slot < 9) srcp = Wp[slot] + n * 128 + k8 * 8;
        else if (slot == 9) srcp = WT + n * 256 + k8 * 8;
        else srcp = WT + n * 256 + 128 + k8 * 8;
        float4 v0 = ((const float4*)srcp)[0];
        float4 v1 = ((const float4*)srcp)[1];
        uint4 hi, lo; cvt8(v0, v1, hi, lo);
        uint32_t off = (uint32_t)slot * 32768u + soff(n, k8 * 8);
        *reinterpret_cast<uint4*>(g_wbh + off) = hi;
        *reinterpret_cast<uint4*>(g_wbl + off) = lo;
    }
}

__global__ void k_count(const int* __restrict__ smask, const int* __restrict__ dst) {
    int e = blockIdx.x * 256 + threadIdx.x;
    int lane = threadIdx.x & 31;
    int sm_ = smask[e];
    int d_ = dst[e];
    unsigned bal = __ballot_sync(0xffffffffu, sm_ == 1);
    if (sm_ == 0) atomicAdd(&g_cnt0[d_], 1);
    int lead = bal ? (__ffs(bal) - 1) : 0;
    int basec = 0;
    if (bal && lane == lead) basec = atomicAdd(&g_mcount, __popc(bal));
    basec = __shfl_sync(0xffffffffu, basec, lead);
    if (sm_ == 1) g_mlist[basec + __popc(bal & ((1u << lane) - 1u))] = e;
}

// ================= node GEMMs: persistent, 9 uniform jobs =================
__global__ void __launch_bounds__(256, 2)
k_nodeg(const float* __restrict__ h, const float* __restrict__ p,
        const float* __restrict__ dv,
        const float* bV1, const float* bV2, const float* bP1,
        const float* bP2, const float* bP3, const float* bD1,
        const float* bD2, const float* bT) {
    extern __shared__ char sm[];
    uint32_t smb = smem_u32(sm);
    int tid = threadIdx.x, lane = tid & 31, wid = tid >> 5;
    int wm = wid & 3, wn = wid >> 2;
    int pidx = blockIdx.x % 9;
    int nct = (gridDim.x - 1 - pidx) / 9 + 1;

    const float* X;
    const float* bias;
    int slot;
    switch (pidx) {
        case 0: X = h;  slot = 0;  bias = bV1; break;
        case 1: X = h;  slot = 1;  bias = bV2; break;
        case 2: X = p;  slot = 2;  bias = bP1; break;
        case 3: X = p;  slot = 3;  bias = bP2; break;
        case 4: X = p;  slot = 4;  bias = bP3; break;
        case 5: X = dv; slot = 5;  bias = bD1; break;
        case 6: X = dv; slot = 6;  bias = bD2; break;
        case 7: X = h;  slot = 9;  bias = bT; break;
        default: X = dv; slot = 10; bias = g_bzero; break;
    }
    if (tid < 128) ((float*)(sm + SM_BIAS))[tid] = bias[tid];
    copy_B(sm, slot, tid);
    float* outp = g_proj[pidx];
    int q = lane >> 2, m = lane & 3;

    for (int t = blockIdx.x / 9; t < NTILE_N; t += nct) {
        int r0 = t * 128;
        __syncthreads();

        float acc[2][8][4];
#pragma unroll
        for (int mf = 0; mf < 2; mf++)
#pragma unroll
            for (int j = 0; j < 8; j++)
#pragma unroll
                for (int i = 0; i < 4; i++) acc[mf][j][i] = 0.f;

        float4 s[4][2];
#pragma unroll
        for (int i = 0; i < 4; i++) {
            int u = tid + i * 256;
            int row = u >> 3, ch = u & 7;
            int g = r0 + row;
            s[i][0] = make_float4(0.f, 0.f, 0.f, 0.f);
            s[i][1] = s[i][0];
            if (g < NN) {
                s[i][0] = ((const float4*)X)[(size_t)g * 32 + ch * 2];
                s[i][1] = ((const float4*)X)[(size_t)g * 32 + ch * 2 + 1];
            }
        }
        stage_sts(sm, tid, s);
        __syncthreads();
        // prefetch kh1 while gemm kh0 runs
#pragma unroll
        for (int i = 0; i < 4; i++) {
            int u = tid + i * 256;
            int row = u >> 3, ch = u & 7;
            int g = r0 + row;
            if (g < NN) {
                s[i][0] = ((const float4*)X)[(size_t)g * 32 + 16 + ch * 2];
                s[i][1] = ((const float4*)X)[(size_t)g * 32 + 16 + ch * 2 + 1];
            } else {
                s[i][0] = make_float4(0.f, 0.f, 0.f, 0.f);
                s[i][1] = s[i][0];
            }
        }
        gemm_half(smb, lane, wm, wn, 0, acc);
        __syncthreads();
        stage_sts(sm, tid, s);
        __syncthreads();
        gemm_half(smb, lane, wm, wn, 1, acc);

        // register epilogue
        const float* bias_s = (const float*)(sm + SM_BIAS);
#pragma unroll
        for (int mf = 0; mf < 2; mf++) {
            int r1 = r0 + wm * 32 + mf * 16 + q;
            int r2 = r1 + 8;
#pragma unroll
            for (int j = 0; j < 8; j++) {
                int col = wn * 64 + j * 8 + m * 2;
                float b0 = bias_s[col], b1 = bias_s[col + 1];
                if (r1 < NN)
                    *(float2*)&outp[(size_t)r1 * DD + col] =
                        make_float2(acc[mf][j][0] + b0, acc[mf][j][1] + b1);
                if (r2 < NN)
                    *(float2*)&outp[(size_t)r2 * DD + col] =
                        make_float2(acc[mf][j][2] + b0, acc[mf][j][3] + b1);
            }
        }
    }
}

// ================= edge pass A: persistent, resident B, smem-C epilogue ==========
__global__ void __launch_bounds__(256, 2)
k_edgeA(const float* __restrict__ e_in, const int* __restrict__ src,
        const int* __restrict__ dst, const int* __restrict__ smask,
        const float* __restrict__ bE1, float* __restrict__ e_out) {
    extern __shared__ char sm[];
    uint32_t smb = smem_u32(sm);
    int tid = threadIdx.x, lane = tid & 31, wid = tid >> 5;
    int wm = wid & 3, wn = wid >> 2;
    int q = lane >> 2, m = lane & 3;

    if (tid < 128) ((float*)(sm + SM_BIAS))[tid] = bE1[tid];
    copy_B(sm, 7, tid);
    const float* P1 = g_proj[2];
    const float* P2 = g_proj[3];

    for (int t = blockIdx.x; t < NTILE_E; t += gridDim.x) {
        int e0 = t * 128;
        __syncthreads();
        if (tid < 128) {
            int eg = e0 + tid;
            ((int*)(sm + SM_ROWA))[tid] = src[eg];
            ((int*)(sm + SM_ROWB))[tid] = dst[eg];
            ((int*)(sm + SM_ROWC))[tid] = smask[eg];
        }
        float4 s[4][2];
#pragma unroll
        for (int i = 0; i < 4; i++) {
            int u = tid + i * 256;
            int row = u >> 3, ch = u & 7;
            s[i][0] = ((const float4*)e_in)[(size_t)(e0 + row) * 32 + ch * 2];
            s[i][1] = ((const float4*)e_in)[(size_t)(e0 + row) * 32 + ch * 2 + 1];
        }
        stage_sts(sm, tid, s);
        __syncthreads();

        float acc[2][8][4];
#pragma unroll
        for (int mf = 0; mf < 2; mf++)
#pragma unroll
            for (int j = 0; j < 8; j++)
#pragma unroll
                for (int i = 0; i < 4; i++) acc[mf][j][i] = 0.f;

#pragma unroll
        for (int i = 0; i < 4; i++) {
            int u = tid + i * 256;
            int row = u >> 3, ch = u & 7;
            s[i][0] = ((const float4*)e_in)[(size_t)(e0 + row) * 32 + 16 + ch * 2];
            s[i][1] = ((const float4*)e_in)[(size_t)(e0 + row) * 32 + 16 + ch * 2 + 1];
        }
        gemm_half(smb, lane, wm, wn, 0, acc);
        __syncthreads();
        stage_sts(sm, tid, s);
        __syncthreads();
        gemm_half(smb, lane, wm, wn, 1, acc);

        // epilogue: 2 passes of 64 rows through swizzled C in the A region
        const float* bias_s = (const float*)(sm + SM_BIAS);
        const int* ssrc = (const int*)(sm + SM_ROWA);
        const int* sdst = (const int*)(sm + SM_ROWB);
        const int* smsk = (const int*)(sm + SM_ROWC);
#pragma unroll
        for (int ph = 0; ph < 2; ph++) {
            __syncthreads();
            if ((wm >> 1) == ph) {
                int wml = wm & 1;
#pragma unroll
                for (int mf = 0; mf < 2; mf++) {
                    int rb = wml * 32 + mf * 16 + q;
#pragma unroll
                    for (int j = 0; j < 8; j++) {
                        int col = wn * 64 + j * 8 + m * 2;
                        int c4 = col >> 2;
                        uint32_t inoff = (uint32_t)((m & 1) * 8);
                        *(float2*)(sm + coff(rb, c4) + inoff) =
                            make_float2(acc[mf][j][0], acc[mf][j][1]);
                        *(float2*)(sm + coff(rb + 8, c4) + inoff) =
                            make_float2(acc[mf][j][2], acc[mf][j][3]);
                    }
                }
            }
            __syncthreads();
            for (int u = tid; u < 2048; u += 256) {
                int r = u >> 5, c4 = u & 31;   // c4 == lane
                int lr = ph * 64 + r;
                int eg = e0 + lr;
                int si = ssrc[lr], di = sdst[lr], msk = smsk[lr];
                float4 cC = *(float4*)(sm + coff(r, c4));
                float4 bv = *(const float4*)&bias_s[c4 * 4];
                float4 p1 = *(const float4*)&P1[(size_t)di * DD + c4 * 4];
                float4 p2 = *(const float4*)&P2[(size_t)si * DD + c4 * 4];
                float4 ev = *(const float4*)&e_in[(size_t)eg * DD + c4 * 4];
                float4 en;
                en.x = 0.5f * (p1.x - p2.x + cC.x + bv.x);
                en.y = 0.5f * (p1.y - p2.y + cC.y + bv.y);
                en.z = 0.5f * (p1.z - p2.z + cC.z + bv.z);
                en.w = 0.5f * (p1.w - p2.w + cC.w + bv.w);
                float4 o;
                o.x = ev.x + lrelu(en.x);
                o.y = ev.y + lrelu(en.y);
                o.z = ev.z + lrelu(en.z);
                o.w = ev.w + lrelu(en.w);
                *(float4*)&e_out[(size_t)eg * DD + c4 * 4] = o;
                if (msk) *(float4*)&g_enew[(size_t)eg * DD + c4 * 4] = en;
                // row-norm: whole row eg lives in this warp (lane == c4)
                float sq = en.x * en.x + en.y * en.y + en.z * en.z + en.w * en.w;
#pragma unroll
                for (int off = 16; off > 0; off >>= 1)
                    sq += __shfl_xor_sync(0xffffffffu, sq, off);
                if (c4 == 0 && msk) g_enorm[eg] = sqrtf(sq);
            }
        }
    }
}

// ================= edge pass B: persistent, resident B, masked V GEMM =============
__global__ void __launch_bounds__(256, 2)
k_edgeB(const float* __restrict__ h, const float* __restrict__ bV,
        const int* __restrict__ src, const int* __restrict__ dst) {
    extern __shared__ char sm[];
    uint32_t smb = smem_u32(sm);
    int tid = threadIdx.x, lane = tid & 31, wid = tid >> 5;
    int wm = wid & 3, wn = wid >> 2;
    int q = lane >> 2, m = lane & 3;
    int mc = g_mcount;
    int ntiles = (mc + 127) >> 7;

    if (tid < 128) ((float*)(sm + SM_BIAS))[tid] = bV[tid];
    copy_B(sm, 8, tid);
    int* seid = (int*)(sm + SM_ROWC);
    int* ssrc = (int*)(sm + SM_ROWA);
    int* sdst = (int*)(sm + SM_ROWB);
    const float* bias_s = (const float*)(sm + SM_BIAS);
    float* svb = (float*)(sm + SM_SV);

    for (int t = blockIdx.x; t < ntiles; t += gridDim.x) {
        int base = t * 128;
        int nt = min(128, mc - base);
        __syncthreads();
        if (tid < 128) {
            int eid = (tid < nt) ? g_mlist[base + tid] : -1;
            seid[tid] = eid;
            ssrc[tid] = (eid >= 0) ? src[eid] : 0;
            sdst[tid] = (eid >= 0) ? dst[eid] : 0;
        }
        __syncthreads();

        float acc[2][8][4];
#pragma unroll
        for (int mf = 0; mf < 2; mf++)
#pragma unroll
            for (int j = 0; j < 8; j++)
#pragma unroll
                for (int i = 0; i < 4; i++) acc[mf][j][i] = 0.f;

        for (int kh = 0; kh < 2; kh++) {
            for (int u = tid; u < 1024; u += 256) {
                int row = u >> 3, ch = u & 7;
                float4 v0 = make_float4(0.f, 0.f, 0.f, 0.f), v1 = v0;
                if (row < nt) {
                    float4 hs0 = ((const float4*)h)[(size_t)ssrc[row] * 32 + kh * 16 + ch * 2];
                    float4 hs1 = ((const float4*)h)[(size_t)ssrc[row] * 32 + kh * 16 + ch * 2 + 1];
                    float4 hd0 = ((const float4*)h)[(size_t)sdst[row] * 32 + kh * 16 + ch * 2];
                    float4 hd1 = ((const float4*)h)[(size_t)sdst[row] * 32 + kh * 16 + ch * 2 + 1];
                    v0.x = hs0.x * hd0.x; v0.y = hs0.y * hd0.y;
                    v0.z = hs0.z * hd0.z; v0.w = hs0.w * hd0.w;
                    v1.x = hs1.x * hd1.x; v1.y = hs1.y * hd1.y;
                    v1.z = hs1.z * hd1.z; v1.w = hs1.w * hd1.w;
                }
                uint4 hi, lo; cvt8(v0, v1, hi, lo);
                uint32_t off = soff64(row, ch * 8);
                *(uint4*)(sm + SM_AH + off) = hi;
                *(uint4*)(sm + SM_AL + off) = lo;
            }
            __syncthreads();
            gemm_half(smb, lane, wm, wn, kh, acc);
            __syncthreads();
        }

        float s0[2] = {0.f, 0.f}, s1[2] = {0.f, 0.f};
#pragma unroll
        for (int mf = 0; mf < 2; mf++)
#pragma unroll
            for (int j = 0; j < 8; j++) {
                float b0 = bias_s[wn * 64 + j * 8 + m * 2];
                float b1 = bias_s[wn * 64 + j * 8 + m * 2 + 1];
                s0[mf] += relu_(acc[mf][j][0] + b0) + relu_(acc[mf][j][1] + b1);
                s1[mf] += relu_(acc[mf][j][2] + b0) + relu_(acc[mf][j][3] + b1);
            }
#pragma unroll
        for (int mf = 0; mf < 2; mf++) {
            s0[mf] += __shfl_xor_sync(0xffffffffu, s0[mf], 1);
            s0[mf] += __shfl_xor_sync(0xffffffffu, s0[mf], 2);
            s1[mf] += __shfl_xor_sync(0xffffffffu, s1[mf], 1);
            s1[mf] += __shfl_xor_sync(0xffffffffu, s1[mf], 2);
        }
        if (m == 0) {
#pragma unroll
            for (int mf = 0; mf < 2; mf++) {
                svb[wn * 128 + wm * 32 + mf * 16 + q] = s0[mf];
                svb[wn * 128 + wm * 32 + mf * 16 + q + 8] = s1[mf];
            }
        }
        __syncthreads();

        // per-edge coefficient into smem
        if (tid < 128) {
            float cf = 0.f;
            if (tid < nt) {
                float sv = svb[tid] + svb[128 + tid];
                float L = g_enorm[seid[tid]];
                if (L > 1e-9f && sv > 0.f) {
                    float r = 0.5f * sqrtf(L);
                    cf = sv * expf(-r / 0.3f) / (1.2f * L * sqrtf(L));
                }
            }
            svb[256 + tid] = cf;
        }
        __syncthreads();

        // cooperative scatter: 256 threads, one float4 chunk each per iter
        const float* scf = svb + 256;
        for (int u = tid; u < 4096; u += 256) {
            int e = u >> 5, c4 = u & 31;
            float cf = scf[e];
            if (cf != 0.f) {
                int eid = seid[e];
                float4 en = ((const float4*)g_enew)[(size_t)eid * 32 + c4];
                float* fp = &g_facc[(size_t)sdst[e] * DD + c4 * 4];
                atomicAdd(fp + 0, cf * en.x);
                atomicAdd(fp + 1, cf * en.y);
                atomicAdd(fp + 2, cf * en.z);
                atomicAdd(fp + 3, cf * en.w);
            }
        }
    }
}

// ================= node finalize =================
__global__ void k_final(const float* __restrict__ h, const float* __restrict__ p,
                        const float* __restrict__ dv, const float* __restrict__ dt,
                        float* __restrict__ out) {
    int w = threadIdx.x >> 5, l = threadIdx.x & 31;
    int n = blockIdx.x * 8 + w;
    int ix = n * 32 + l;
    const float4* V1 = (const float4*)g_proj[0];
    const float4* V2 = (const float4*)g_proj[1];
    const float4* P3 = (const float4*)g_proj[4];
    const float4* D1 = (const float4*)g_proj[5];
    const float4* D2 = (const float4*)g_proj[6];
    const float4* TA = (const float4*)g_proj[7];
    const float4* TB = (const float4*)g_proj[8];
    const float4* FA = (const float4*)g_facc;

    float4 v1 = V1[ix], v2 = V2[ix], p3 = P3[ix], d1 = D1[ix], d2 = D2[ix];
    float4 ta = TA[ix], tb = TB[ix], fa = FA[ix];
    float cnt = (float)g_cnt0[n];

    float4 th;
    th.x = ta.x + tb.x; th.y = ta.y + tb.y;
    th.z = ta.z + tb.z; th.w = ta.w + tb.w;

    float4 f;
    f.x = (d1.x - v1.x) * (cnt * relu_(th.x)) + fa.x;
    f.y = (d1.y - v1.y) * (cnt * relu_(th.y)) + fa.y;
    f.z = (d1.z - v1.z) * (cnt * relu_(th.z)) + fa.z;
    f.w = (d1.w - v1.w) * (cnt * relu_(th.w)) + fa.w;

    float sq = f.x * f.x + f.y * f.y + f.z * f.z + f.w * f.w;
#pragma unroll
    for (int off = 16; off > 0; off >>= 1) sq += __shfl_xor_sync(0xffffffffu, sq, off);
    float inv = 1.f / (sqrtf(sq) + 1e-9f);

    float dtv = dt[n];
    float dtp = dtv + 0.5f * dtv * dtv;

    float4 hv = ((const float4*)h)[ix];
    float4 pv = ((const float4*)p)[ix];
    float4 dvv = ((const float4*)dv)[ix];

    float4 ho, po, dq;
    ho.x = hv.x + lrelu(v2.x + f.x * dtv);
    ho.y = hv.y + lrelu(v2.y + f.y * dtv);
    ho.z = hv.z + lrelu(v2.z + f.z * dtv);
    ho.w = hv.w + lrelu(v2.w + f.w * dtv);
    po.x = pv.x + lrelu(p3.x + f.x * dtp);
    po.y = pv.y + lrelu(p3.y + f.y * dtp);
    po.z = pv.z + lrelu(p3.z + f.z * dtp);
    po.w = pv.w + lrelu(p3.w + f.w * dtp);
    dq.x = dvv.x + lrelu(d2.x + f.x * inv);
    dq.y = dvv.y + lrelu(d2.y + f.y * inv);
    dq.z = dvv.z + lrelu(d2.z + f.z * inv);
    dq.w = dvv.w + lrelu(d2.w + f.w * inv);

    float4* outH = (float4*)out;
    float4* outP = (float4*)(out + (size_t)NN * DD + (size_t)EE * DD);
    float4* outD = (float4*)(out + 2 * (size_t)NN * DD + (size_t)EE * DD);
    outH[ix] = ho;
    outP[ix] = po;
    outD[ix] = dq;
}

// ================= launch =================
extern "C" void kernel_launch(void* const* d_in, const int* in_sizes, int n_in,
                              void* d_out, int out_size) {
    const float* h   = (const float*)d_in[0];
    const float* e   = (const float*)d_in[1];
    const float* p   = (const float*)d_in[2];
    const float* dv  = (const float*)d_in[3];
    const float* dt  = (const float*)d_in[4];
    const int* smask = (const int*)d_in[5];
    const int* src   = (const int*)d_in[6];
    const int* dst   = (const int*)d_in[7];
    const float* W_V1 = (const float*)d_in[8],  *b_V1 = (const float*)d_in[9];
    const float* W_V2 = (const float*)d_in[10], *b_V2 = (const float*)d_in[11];
    const float* W_E1 = (const float*)d_in[12], *b_E1 = (const float*)d_in[13];
    const float* W_P1 = (const float*)d_in[14], *b_P1 = (const float*)d_in[15];
    const float* W_P2 = (const float*)d_in[16], *b_P2 = (const float*)d_in[17];
    const float* W_P3 = (const float*)d_in[18], *b_P3 = (const float*)d_in[19];
    const float* W_D1 = (const float*)d_in[20], *b_D1 = (const float*)d_in[21];
    const float* W_D2 = (const float*)d_in[22], *b_D2 = (const float*)d_in[23];
    const float* W_V  = (const float*)d_in[24], *b_V  = (const float*)d_in[25];
    const float* W_T  = (const float*)d_in[26], *b_T  = (const float*)d_in[27];
    float* out = (float*)d_out;

    cudaFuncSetAttribute(k_nodeg, cudaFuncAttributeMaxDynamicSharedMemorySize, SM_TOTAL);
    cudaFuncSetAttribute(k_edgeA, cudaFuncAttributeMaxDynamicSharedMemorySize, SM_TOTAL);
    cudaFuncSetAttribute(k_edgeB, cudaFuncAttributeMaxDynamicSharedMemorySize, SM_TOTAL);

    k_prep<<<640, 256>>>(W_V1, W_V2, W_P1, W_P2, W_P3, W_D1, W_D2, W_E1, W_V, W_T);
    k_count<<<EE / 256, 256>>>(smask, dst);
    k_nodeg<<<GRID_P, 256, SM_TOTAL>>>(h, p, dv, b_V1, b_V2, b_P1, b_P2, b_P3,
                                       b_D1, b_D2, b_T);
    k_edgeA<<<GRID_P, 256, SM_TOTAL>>>(e, src, dst, smask, b_E1, out + (size_t)NN * DD);
    k_edgeB<<<GRID_P, 256, SM_TOTAL>>>(h, b_V, src, dst);
    k_final<<<NN / 8, 256>>>(h, p, dv, dt, out);
}

// round 9
// speedup vs baseline: 1.4976x; 1.0406x over previous
#include <cuda_runtime.h>
#include <cuda_bf16.h>
#include <cstdint>
#include <math.h>

#define NN 10000
#define EE 320000
#define DD 128
#define NTILE_N 79      /* (NN+127)/128 */
#define NTILE_E 2500    /* EE/128 */
#define GRID_P 296      /* persistent grid: 148 SMs x 2 CTAs */

// ================= static device scratch =================
__device__ float g_proj[9][NN * DD];     // V1h V2h P1h P2h P3h D1h D2h ThA ThB
__device__ float g_enew[(size_t)EE * DD];
__device__ float g_enorm[EE];
__device__ float g_facc[NN * DD];
__device__ int   g_cnt0[NN];
__device__ int   g_mlist[EE];
__device__ int   g_mcount;
__device__ float g_bzero[DD];            // stays zero (module-load init)
// pre-split weight tiles in swizzled layout (32KB each):
// slots 0..6 node W (V1,V2,P1,P2,P3,D1,D2), 7 E1, 8 V, 9/10 = W_T halves
__device__ __align__(16) unsigned char g_wbh[11 * 32768];
__device__ __align__(16) unsigned char g_wbl[11 * 32768];

__device__ __forceinline__ float lrelu(float x) { return x > 0.f ? x : 0.01f * x; }
__device__ __forceinline__ float relu_(float x) { return x > 0.f ? x : 0.f; }

__device__ __forceinline__ uint32_t smem_u32(const void* p) {
    uint32_t a;
    asm("{ .reg .u64 t; cvta.to.shared.u64 t, %1; cvt.u32.u64 %0, t; }" : "=r"(a) : "l"(p));
    return a;
}
__device__ __forceinline__ uint32_t pack2(__nv_bfloat16 a, __nv_bfloat16 b) {
    __nv_bfloat162 t; t.x = a; t.y = b;
    return *reinterpret_cast<uint32_t*>(&t);
}

// swizzled byte offset inside a 128x128 bf16 tile (B tiles): row stride 256B
__device__ __forceinline__ uint32_t soff(int r, int c) {
    return (uint32_t)((r << 8) + ((((c >> 3) ^ (r & 7)) << 4) | ((c & 7) << 1)));
}
// swizzled byte offset inside a 128x64 bf16 tile (A half-tiles): row stride 128B
__device__ __forceinline__ uint32_t soff64(int r, int c) {
    return (uint32_t)((r << 7) + (((((c >> 3) ^ (r & 7)) & 7) << 4) | ((c & 7) << 1)));
}

__device__ __forceinline__ void ldsm4(uint32_t* r, uint32_t addr) {
    asm volatile("ldmatrix.sync.aligned.m8n8.x4.shared.b16 {%0,%1,%2,%3}, [%4];"
                 : "=r"(r[0]), "=r"(r[1]), "=r"(r[2]), "=r"(r[3]) : "r"(addr));
}
__device__ __forceinline__ void mma16816(float* d, const uint32_t* a,
                                         uint32_t b0, uint32_t b1) {
    asm volatile(
        "mma.sync.aligned.m16n8k16.row.col.f32.bf16.bf16.f32 "
        "{%0,%1,%2,%3}, {%4,%5,%6,%7}, {%8,%9}, {%0,%1,%2,%3};"
        : "+f"(d[0]), "+f"(d[1]), "+f"(d[2]), "+f"(d[3])
        : "r"(a[0]), "r"(a[1]), "r"(a[2]), "r"(a[3]), "r"(b0), "r"(b1));
}

// split 8 fp32 -> hi/lo bf16x2 quads
__device__ __forceinline__ void cvt8(float4 v0, float4 v1, uint4& hi, uint4& lo) {
    __nv_bfloat16 a0 = __float2bfloat16(v0.x), a1 = __float2bfloat16(v0.y);
    __nv_bfloat16 a2 = __float2bfloat16(v0.z), a3 = __float2bfloat16(v0.w);
    __nv_bfloat16 a4 = __float2bfloat16(v1.x), a5 = __float2bfloat16(v1.y);
    __nv_bfloat16 a6 = __float2bfloat16(v1.z), a7 = __float2bfloat16(v1.w);
    hi.x = pack2(a0, a1); hi.y = pack2(a2, a3);
    hi.z = pack2(a4, a5); hi.w = pack2(a6, a7);
    lo.x = pack2(__float2bfloat16(v0.x - __bfloat162float(a0)),
                 __float2bfloat16(v0.y - __bfloat162float(a1)));
    lo.y = pack2(__float2bfloat16(v0.z - __bfloat162float(a2)),
                 __float2bfloat16(v0.w - __bfloat162float(a3)));
    lo.z = pack2(__float2bfloat16(v1.x - __bfloat162float(a4)),
                 __float2bfloat16(v1.y - __bfloat162float(a5)));
    lo.w = pack2(__float2bfloat16(v1.z - __bfloat162float(a6)),
                 __float2bfloat16(v1.w - __bfloat162float(a7)));
}

// shared memory layout (102400 bytes -> 2 CTAs/SM)
#define SM_BIAS 0
#define SM_ROWA 512
#define SM_ROWB 1024
#define SM_ROWC 1536
#define SM_SV   2048
#define SM_AH   4096                 /* 128x64 bf16 hi (16KB) */
#define SM_AL   (4096 + 16384)       /* 128x64 bf16 lo (16KB) */
#define SM_BH   (4096 + 32768)       /* 128x128 bf16 hi (32KB) RESIDENT */
#define SM_BL   (4096 + 65536)       /* 128x128 bf16 lo (32KB) RESIDENT */
#define SM_C    4096                 /* fp32 C 64rows x 512B, overlays A only */
#define SM_TOTAL (4096 + 98304)

// C chunk-swizzled offset: local row r (0..63), float4-chunk c4 (0..31)
__device__ __forceinline__ uint32_t coff(int r, int c4) {
    return (uint32_t)(SM_C + r * 512 + (((c4 ^ (r & 7)) & 31) << 4));
}

// ---- 3-term split GEMM over one K-half, warp tile 32(M) x 64(N), 8 warps ----
// B fragments double-buffered: bn+1's ldsm issued before bn's MMAs
__device__ __forceinline__ void gemm_half(uint32_t smb, int lane, int wm, int wn,
                                          int kh, float (&acc)[2][8][4]) {
    const int fr = lane & 15;
    const int fc = (lane >> 4) << 3;
    const int m0 = wm * 32;
    const int n0 = wn * 64;
#pragma unroll
    for (int ks = 0; ks < 4; ks++) {
        const int kc = kh * 64 + ks * 16 + fc;
        uint32_t aH[2][4], aL[2][4];
        uint32_t bH[2][4], bL[2][4];
        ldsm4(aH[0], smb + SM_AH + soff64(m0 + fr, ks * 16 + fc));
        ldsm4(aH[1], smb + SM_AH + soff64(m0 + 16 + fr, ks * 16 + fc));
        ldsm4(bH[0], smb + SM_BH + soff(n0 + fr, kc));
        ldsm4(bL[0], smb + SM_BL + soff(n0 + fr, kc));
        ldsm4(aL[0], smb + SM_AL + soff64(m0 + fr, ks * 16 + fc));
        ldsm4(aL[1], smb + SM_AL + soff64(m0 + 16 + fr, ks * 16 + fc));
        int cur = 0;
#pragma unroll
        for (int bn = 0; bn < 4; bn++) {
            int nxt = cur ^ 1;
            if (bn < 3) {
                ldsm4(bH[nxt], smb + SM_BH + soff(n0 + (bn + 1) * 16 + fr, kc));
                ldsm4(bL[nxt], smb + SM_BL + soff(n0 + (bn + 1) * 16 + fr, kc));
            }
#pragma unroll
            for (int mf = 0; mf < 2; mf++) {
                mma16816(acc[mf][2 * bn],     aH[mf], bH[cur][0], bH[cur][2]);
                mma16816(acc[mf][2 * bn + 1], aH[mf], bH[cur][1], bH[cur][3]);
                mma16816(acc[mf][2 * bn],     aL[mf], bH[cur][0], bH[cur][2]);
                mma16816(acc[mf][2 * bn + 1], aL[mf], bH[cur][1], bH[cur][3]);
                mma16816(acc[mf][2 * bn],     aH[mf], bL[cur][0], bL[cur][2]);
                mma16816(acc[mf][2 * bn + 1], aH[mf], bL[cur][1], bL[cur][3]);
            }
            cur = nxt;
        }
    }
}

__device__ __forceinline__ void copy_B(char* sm, int slot, int tid) {
    const uint4* gh = (const uint4*)(g_wbh + slot * 32768);
    const uint4* gl = (const uint4*)(g_wbl + slot * 32768);
    uint4* bh = (uint4*)(sm + SM_BH);
    uint4* bl = (uint4*)(sm + SM_BL);
    for (int i = tid; i < 2048; i += 256) { bh[i] = gh[i]; bl[i] = gl[i]; }
}

// store prefetched regs (one K-half of A) into swizzled smem
__device__ __forceinline__ void stage_sts(char* sm, int tid, const float4 (&s)[4][2]) {
#pragma unroll
    for (int i = 0; i < 4; i++) {
        int u = tid + i * 256;
        int row = u >> 3, ch = u & 7;
        uint4 hi, lo; cvt8(s[i][0], s[i][1], hi, lo);
        uint32_t off = soff64(row, ch * 8);
        *(uint4*)(sm + SM_AH + off) = hi;
        *(uint4*)(sm + SM_AL + off) = lo;
    }
}

// ================= prep: zero scratch + weight split/swizzle =================
__global__ void k_prep(const float* W0, const float* W1, const float* W2, const float* W3,
                       const float* W4, const float* W5, const float* W6, const float* W7,
                       const float* W8, const float* WT) {
    const float* Wp[9] = {W0, W1, W2, W3, W4, W5, W6, W7, W8};
    int i = blockIdx.x * blockDim.x + threadIdx.x;
    int stride = gridDim.x * blockDim.x;
    for (int t = i; t < NN * DD; t += stride) g_facc[t] = 0.f;
    for (int t = i; t < NN; t += stride) g_cnt0[t] = 0;
    if (i == 0) g_mcount = 0;
    for (int t = i; t < 11 * 2048; t += stride) {
        int slot = t >> 11, r = t & 2047;
        int n = r >> 4, k8 = r & 15;
        const float* srcp;
        if (slot < 9) srcp = Wp[slot] + n * 128 + k8 * 8;
        else if (slot == 9) srcp = WT + n * 256 + k8 * 8;
        else srcp = WT + n * 256 + 128 + k8 * 8;
        float4 v0 = ((const float4*)srcp)[0];
        float4 v1 = ((const float4*)srcp)[1];
        uint4 hi, lo; cvt8(v0, v1, hi, lo);
        uint32_t off = (uint32_t)slot * 32768u + soff(n, k8 * 8);
        *reinterpret_cast<uint4*>(g_wbh + off) = hi;
        *reinterpret_cast<uint4*>(g_wbl + off) = lo;
    }
}

__global__ void k_count(const int* __restrict__ smask, const int* __restrict__ dst) {
    int e = blockIdx.x * 256 + threadIdx.x;
    int lane = threadIdx.x & 31;
    int sm_ = smask[e];
    int d_ = dst[e];
    unsigned bal = __ballot_sync(0xffffffffu, sm_ == 1);
    if (sm_ == 0) atomicAdd(&g_cnt0[d_], 1);
    int lead = bal ? (__ffs(bal) - 1) : 0;
    int basec = 0;
    if (bal && lane == lead) basec = atomicAdd(&g_mcount, __popc(bal));
    basec = __shfl_sync(0xffffffffu, basec, lead);
    if (sm_ == 1) g_mlist[basec + __popc(bal & ((1u << lane) - 1u))] = e;
}

// ================= node GEMMs: persistent, 9 uniform jobs =================
__global__ void __launch_bounds__(256, 2)
k_nodeg(const float* __restrict__ h, const float* __restrict__ p,
        const float* __restrict__ dv,
        const float* bV1, const float* bV2, const float* bP1,
        const float* bP2, const float* bP3, const float* bD1,
        const float* bD2, const float* bT) {
    extern __shared__ char sm[];
    uint32_t smb = smem_u32(sm);
    int tid = threadIdx.x, lane = tid & 31, wid = tid >> 5;
    int wm = wid & 3, wn = wid >> 2;
    int pidx = blockIdx.x % 9;
    int nct = (gridDim.x - 1 - pidx) / 9 + 1;

    const float* X;
    const float* bias;
    int slot;
    switch (pidx) {
        case 0: X = h;  slot = 0;  bias = bV1; break;
        case 1: X = h;  slot = 1;  bias = bV2; break;
        case 2: X = p;  slot = 2;  bias = bP1; break;
        case 3: X = p;  slot = 3;  bias = bP2; break;
        case 4: X = p;  slot = 4;  bias = bP3; break;
        case 5: X = dv; slot = 5;  bias = bD1; break;
        case 6: X = dv; slot = 6;  bias = bD2; break;
        case 7: X = h;  slot = 9;  bias = bT; break;
        default: X = dv; slot = 10; bias = g_bzero; break;
    }
    if (tid < 128) ((float*)(sm + SM_BIAS))[tid] = bias[tid];
    copy_B(sm, slot, tid);
    float* outp = g_proj[pidx];
    int q = lane >> 2, m = lane & 3;

    for (int t = blockIdx.x / 9; t < NTILE_N; t += nct) {
        int r0 = t * 128;
        __syncthreads();

        float acc[2][8][4];
#pragma unroll
        for (int mf = 0; mf < 2; mf++)
#pragma unroll
            for (int j = 0; j < 8; j++)
#pragma unroll
                for (int i = 0; i < 4; i++) acc[mf][j][i] = 0.f;

        float4 s[4][2];
#pragma unroll
        for (int i = 0; i < 4; i++) {
            int u = tid + i * 256;
            int row = u >> 3, ch = u & 7;
            int g = r0 + row;
            s[i][0] = make_float4(0.f, 0.f, 0.f, 0.f);
            s[i][1] = s[i][0];
            if (g < NN) {
                s[i][0] = ((const float4*)X)[(size_t)g * 32 + ch * 2];
                s[i][1] = ((const float4*)X)[(size_t)g * 32 + ch * 2 + 1];
            }
        }
        stage_sts(sm, tid, s);
        __syncthreads();
        // prefetch kh1 while gemm kh0 runs
#pragma unroll
        for (int i = 0; i < 4; i++) {
            int u = tid + i * 256;
            int row = u >> 3, ch = u & 7;
            int g = r0 + row;
            if (g < NN) {
                s[i][0] = ((const float4*)X)[(size_t)g * 32 + 16 + ch * 2];
                s[i][1] = ((const float4*)X)[(size_t)g * 32 + 16 + ch * 2 + 1];
            } else {
                s[i][0] = make_float4(0.f, 0.f, 0.f, 0.f);
                s[i][1] = s[i][0];
            }
        }
        gemm_half(smb, lane, wm, wn, 0, acc);
        __syncthreads();
        stage_sts(sm, tid, s);
        __syncthreads();
        gemm_half(smb, lane, wm, wn, 1, acc);

        // register epilogue
        const float* bias_s = (const float*)(sm + SM_BIAS);
#pragma unroll
        for (int mf = 0; mf < 2; mf++) {
            int r1 = r0 + wm * 32 + mf * 16 + q;
            int r2 = r1 + 8;
#pragma unroll
            for (int j = 0; j < 8; j++) {
                int col = wn * 64 + j * 8 + m * 2;
                float b0 = bias_s[col], b1 = bias_s[col + 1];
                if (r1 < NN)
                    *(float2*)&outp[(size_t)r1 * DD + col] =
                        make_float2(acc[mf][j][0] + b0, acc[mf][j][1] + b1);
                if (r2 < NN)
                    *(float2*)&outp[(size_t)r2 * DD + col] =
                        make_float2(acc[mf][j][2] + b0, acc[mf][j][3] + b1);
            }
        }
    }
}

// ================= edge pass A: persistent, resident B, smem-C epilogue ==========
__global__ void __launch_bounds__(256, 2)
k_edgeA(const float* __restrict__ e_in, const int* __restrict__ src,
        const int* __restrict__ dst, const int* __restrict__ smask,
        const float* __restrict__ bE1, float* __restrict__ e_out) {
    extern __shared__ char sm[];
    uint32_t smb = smem_u32(sm);
    int tid = threadIdx.x, lane = tid & 31, wid = tid >> 5;
    int wm = wid & 3, wn = wid >> 2;
    int q = lane >> 2, m = lane & 3;

    if (tid < 128) ((float*)(sm + SM_BIAS))[tid] = bE1[tid];
    copy_B(sm, 7, tid);
    const float* P1 = g_proj[2];
    const float* P2 = g_proj[3];

    for (int t = blockIdx.x; t < NTILE_E; t += gridDim.x) {
        int e0 = t * 128;
        __syncthreads();
        if (tid < 128) {
            int eg = e0 + tid;
            ((int*)(sm + SM_ROWA))[tid] = src[eg];
            ((int*)(sm + SM_ROWB))[tid] = dst[eg];
            ((int*)(sm + SM_ROWC))[tid] = smask[eg];
        }
        float4 s[4][2];
#pragma unroll
        for (int i = 0; i < 4; i++) {
            int u = tid + i * 256;
            int row = u >> 3, ch = u & 7;
            s[i][0] = ((const float4*)e_in)[(size_t)(e0 + row) * 32 + ch * 2];
            s[i][1] = ((const float4*)e_in)[(size_t)(e0 + row) * 32 + ch * 2 + 1];
        }
        stage_sts(sm, tid, s);
        __syncthreads();

        float acc[2][8][4];
#pragma unroll
        for (int mf = 0; mf < 2; mf++)
#pragma unroll
            for (int j = 0; j < 8; j++)
#pragma unroll
                for (int i = 0; i < 4; i++) acc[mf][j][i] = 0.f;

#pragma unroll
        for (int i = 0; i < 4; i++) {
            int u = tid + i * 256;
            int row = u >> 3, ch = u & 7;
            s[i][0] = ((const float4*)e_in)[(size_t)(e0 + row) * 32 + 16 + ch * 2];
            s[i][1] = ((const float4*)e_in)[(size_t)(e0 + row) * 32 + 16 + ch * 2 + 1];
        }
        gemm_half(smb, lane, wm, wn, 0, acc);
        __syncthreads();
        stage_sts(sm, tid, s);
        __syncthreads();
        gemm_half(smb, lane, wm, wn, 1, acc);

        // epilogue: 2 passes of 64 rows through swizzled C in the A region
        const float* bias_s = (const float*)(sm + SM_BIAS);
        const int* ssrc = (const int*)(sm + SM_ROWA);
        const int* sdst = (const int*)(sm + SM_ROWB);
        const int* smsk = (const int*)(sm + SM_ROWC);
#pragma unroll
        for (int ph = 0; ph < 2; ph++) {
            __syncthreads();
            if ((wm >> 1) == ph) {
                int wml = wm & 1;
#pragma unroll
                for (int mf = 0; mf < 2; mf++) {
                    int rb = wml * 32 + mf * 16 + q;
#pragma unroll
                    for (int j = 0; j < 8; j++) {
                        int col = wn * 64 + j * 8 + m * 2;
                        int c4 = col >> 2;
                        uint32_t inoff = (uint32_t)((m & 1) * 8);
                        *(float2*)(sm + coff(rb, c4) + inoff) =
                            make_float2(acc[mf][j][0], acc[mf][j][1]);
                        *(float2*)(sm + coff(rb + 8, c4) + inoff) =
                            make_float2(acc[mf][j][2], acc[mf][j][3]);
                    }
                }
            }
            __syncthreads();
            for (int u = tid; u < 2048; u += 256) {
                int r = u >> 5, c4 = u & 31;   // c4 == lane
                int lr = ph * 64 + r;
                int eg = e0 + lr;
                int si = ssrc[lr], di = sdst[lr], msk = smsk[lr];
                float4 cC = *(float4*)(sm + coff(r, c4));
                float4 bv = *(const float4*)&bias_s[c4 * 4];
                float4 p1 = *(const float4*)&P1[(size_t)di * DD + c4 * 4];
                float4 p2 = *(const float4*)&P2[(size_t)si * DD + c4 * 4];
                float4 ev = *(const float4*)&e_in[(size_t)eg * DD + c4 * 4];
                float4 en;
                en.x = 0.5f * (p1.x - p2.x + cC.x + bv.x);
                en.y = 0.5f * (p1.y - p2.y + cC.y + bv.y);
                en.z = 0.5f * (p1.z - p2.z + cC.z + bv.z);
                en.w = 0.5f * (p1.w - p2.w + cC.w + bv.w);
                float4 o;
                o.x = ev.x + lrelu(en.x);
                o.y = ev.y + lrelu(en.y);
                o.z = ev.z + lrelu(en.z);
                o.w = ev.w + lrelu(en.w);
                *(float4*)&e_out[(size_t)eg * DD + c4 * 4] = o;
                if (msk) *(float4*)&g_enew[(size_t)eg * DD + c4 * 4] = en;
                // row-norm: whole row eg lives in this warp (lane == c4)
                float sq = en.x * en.x + en.y * en.y + en.z * en.z + en.w * en.w;
#pragma unroll
                for (int off = 16; off > 0; off >>= 1)
                    sq += __shfl_xor_sync(0xffffffffu, sq, off);
                if (c4 == 0 && msk) g_enorm[eg] = sqrtf(sq);
            }
        }
    }
}

// ================= edge pass B: persistent, resident B, masked V GEMM =============
__global__ void __launch_bounds__(256, 2)
k_edgeB(const float* __restrict__ h, const float* __restrict__ bV,
        const int* __restrict__ src, const int* __restrict__ dst) {
    extern __shared__ char sm[];
    uint32_t smb = smem_u32(sm);
    int tid = threadIdx.x, lane = tid & 31, wid = tid >> 5;
    int wm = wid & 3, wn = wid >> 2;
    int q = lane >> 2, m = lane & 3;
    int mc = g_mcount;
    int ntiles = (mc + 127) >> 7;

    if (tid < 128) ((float*)(sm + SM_BIAS))[tid] = bV[tid];
    copy_B(sm, 8, tid);
    int* seid = (int*)(sm + SM_ROWC);
    int* ssrc = (int*)(sm + SM_ROWA);
    int* sdst = (int*)(sm + SM_ROWB);
    const float* bias_s = (const float*)(sm + SM_BIAS);
    float* svb = (float*)(sm + SM_SV);

    for (int t = blockIdx.x; t < ntiles; t += gridDim.x) {
        int base = t * 128;
        int nt = min(128, mc - base);
        __syncthreads();
        if (tid < 128) {
            int eid = (tid < nt) ? g_mlist[base + tid] : -1;
            seid[tid] = eid;
            ssrc[tid] = (eid >= 0) ? src[eid] : 0;
            sdst[tid] = (eid >= 0) ? dst[eid] : 0;
        }
        __syncthreads();

        float acc[2][8][4];
#pragma unroll
        for (int mf = 0; mf < 2; mf++)
#pragma unroll
            for (int j = 0; j < 8; j++)
#pragma unroll
                for (int i = 0; i < 4; i++) acc[mf][j][i] = 0.f;

        for (int kh = 0; kh < 2; kh++) {
            for (int u = tid; u < 1024; u += 256) {
                int row = u >> 3, ch = u & 7;
                float4 v0 = make_float4(0.f, 0.f, 0.f, 0.f), v1 = v0;
                if (row < nt) {
                    float4 hs0 = ((const float4*)h)[(size_t)ssrc[row] * 32 + kh * 16 + ch * 2];
                    float4 hs1 = ((const float4*)h)[(size_t)ssrc[row] * 32 + kh * 16 + ch * 2 + 1];
                    float4 hd0 = ((const float4*)h)[(size_t)sdst[row] * 32 + kh * 16 + ch * 2];
                    float4 hd1 = ((const float4*)h)[(size_t)sdst[row] * 32 + kh * 16 + ch * 2 + 1];
                    v0.x = hs0.x * hd0.x; v0.y = hs0.y * hd0.y;
                    v0.z = hs0.z * hd0.z; v0.w = hs0.w * hd0.w;
                    v1.x = hs1.x * hd1.x; v1.y = hs1.y * hd1.y;
                    v1.z = hs1.z * hd1.z; v1.w = hs1.w * hd1.w;
                }
                uint4 hi, lo; cvt8(v0, v1, hi, lo);
                uint32_t off = soff64(row, ch * 8);
                *(uint4*)(sm + SM_AH + off) = hi;
                *(uint4*)(sm + SM_AL + off) = lo;
            }
            __syncthreads();
            gemm_half(smb, lane, wm, wn, kh, acc);
            __syncthreads();
        }

        float s0[2] = {0.f, 0.f}, s1[2] = {0.f, 0.f};
#pragma unroll
        for (int mf = 0; mf < 2; mf++)
#pragma unroll
            for (int j = 0; j < 8; j++) {
                float b0 = bias_s[wn * 64 + j * 8 + m * 2];
                float b1 = bias_s[wn * 64 + j * 8 + m * 2 + 1];
                s0[mf] += relu_(acc[mf][j][0] + b0) + relu_(acc[mf][j][1] + b1);
                s1[mf] += relu_(acc[mf][j][2] + b0) + relu_(acc[mf][j][3] + b1);
            }
#pragma unroll
        for (int mf = 0; mf < 2; mf++) {
            s0[mf] += __shfl_xor_sync(0xffffffffu, s0[mf], 1);
            s0[mf] += __shfl_xor_sync(0xffffffffu, s0[mf], 2);
            s1[mf] += __shfl_xor_sync(0xffffffffu, s1[mf], 1);
            s1[mf] += __shfl_xor_sync(0xffffffffu, s1[mf], 2);
        }
        if (m == 0) {
#pragma unroll
            for (int mf = 0; mf < 2; mf++) {
                svb[wn * 128 + wm * 32 + mf * 16 + q] = s0[mf];
                svb[wn * 128 + wm * 32 + mf * 16 + q + 8] = s1[mf];
            }
        }
        __syncthreads();

        // per-edge coefficient into smem
        if (tid < 128) {
            float cf = 0.f;
            if (tid < nt) {
                float sv = svb[tid] + svb[128 + tid];
                float L = g_enorm[seid[tid]];
                if (L > 1e-9f && sv > 0.f) {
                    float r = 0.5f * sqrtf(L);
                    cf = sv * expf(-r / 0.3f) / (1.2f * L * sqrtf(L));
                }
            }
            svb[256 + tid] = cf;
        }
        __syncthreads();

        // cooperative scatter: 256 threads, one float4 chunk each, v4 reductions
        const float* scf = svb + 256;
        for (int u = tid; u < 4096; u += 256) {
            int e = u >> 5, c4 = u & 31;
            float cf = scf[e];
            if (cf != 0.f) {
                int eid = seid[e];
                float4 en = ((const float4*)g_enew)[(size_t)eid * 32 + c4];
                float* fp = &g_facc[(size_t)sdst[e] * DD + c4 * 4];
                asm volatile(
                    "red.global.add.v4.f32 [%0], {%1, %2, %3, %4};"
                    :: "l"(fp), "f"(cf * en.x), "f"(cf * en.y),
                       "f"(cf * en.z), "f"(cf * en.w)
                    : "memory");
            }
        }
    }
}

// ================= node finalize =================
__global__ void k_final(const float* __restrict__ h, const float* __restrict__ p,
                        const float* __restrict__ dv, const float* __restrict__ dt,
                        float* __restrict__ out) {
    int w = threadIdx.x >> 5, l = threadIdx.x & 31;
    int n = blockIdx.x * 8 + w;
    int ix = n * 32 + l;
    const float4* V1 = (const float4*)g_proj[0];
    const float4* V2 = (const float4*)g_proj[1];
    const float4* P3 = (const float4*)g_proj[4];
    const float4* D1 = (const float4*)g_proj[5];
    const float4* D2 = (const float4*)g_proj[6];
    const float4* TA = (const float4*)g_proj[7];
    const float4* TB = (const float4*)g_proj[8];
    const float4* FA = (const float4*)g_facc;

    float4 v1 = V1[ix], v2 = V2[ix], p3 = P3[ix], d1 = D1[ix], d2 = D2[ix];
    float4 ta = TA[ix], tb = TB[ix], fa = FA[ix];
    float cnt = (float)g_cnt0[n];

    float4 th;
    th.x = ta.x + tb.x; th.y = ta.y + tb.y;
    th.z = ta.z + tb.z; th.w = ta.w + tb.w;

    float4 f;
    f.x = (d1.x - v1.x) * (cnt * relu_(th.x)) + fa.x;
    f.y = (d1.y - v1.y) * (cnt * relu_(th.y)) + fa.y;
    f.z = (d1.z - v1.z) * (cnt * relu_(th.z)) + fa.z;
    f.w = (d1.w - v1.w) * (cnt * relu_(th.w)) + fa.w;

    float sq = f.x * f.x + f.y * f.y + f.z * f.z + f.w * f.w;
#pragma unroll
    for (int off = 16; off > 0; off >>= 1) sq += __shfl_xor_sync(0xffffffffu, sq, off);
    float inv = 1.f / (sqrtf(sq) + 1e-9f);

    float dtv = dt[n];
    float dtp = dtv + 0.5f * dtv * dtv;

    float4 hv = ((const float4*)h)[ix];
    float4 pv = ((const float4*)p)[ix];
    float4 dvv = ((const float4*)dv)[ix];

    float4 ho, po, dq;
    ho.x = hv.x + lrelu(v2.x + f.x * dtv);
    ho.y = hv.y + lrelu(v2.y + f.y * dtv);
    ho.z = hv.z + lrelu(v2.z + f.z * dtv);
    ho.w = hv.w + lrelu(v2.w + f.w * dtv);
    po.x = pv.x + lrelu(p3.x + f.x * dtp);
    po.y = pv.y + lrelu(p3.y + f.y * dtp);
    po.z = pv.z + lrelu(p3.z + f.z * dtp);
    po.w = pv.w + lrelu(p3.w + f.w * dtp);
    dq.x = dvv.x + lrelu(d2.x + f.x * inv);
    dq.y = dvv.y + lrelu(d2.y + f.y * inv);
    dq.z = dvv.z + lrelu(d2.z + f.z * inv);
    dq.w = dvv.w + lrelu(d2.w + f.w * inv);

    float4* outH = (float4*)out;
    float4* outP = (float4*)(out + (size_t)NN * DD + (size_t)EE * DD);
    float4* outD = (float4*)(out + 2 * (size_t)NN * DD + (size_t)EE * DD);
    outH[ix] = ho;
    outP[ix] = po;
    outD[ix] = dq;
}

// ================= launch =================
extern "C" void kernel_launch(void* const* d_in, const int* in_sizes, int n_in,
                              void* d_out, int out_size) {
    const float* h   = (const float*)d_in[0];
    const float* e   = (const float*)d_in[1];
    const float* p   = (const float*)d_in[2];
    const float* dv  = (const float*)d_in[3];
    const float* dt  = (const float*)d_in[4];
    const int* smask = (const int*)d_in[5];
    const int* src   = (const int*)d_in[6];
    const int* dst   = (const int*)d_in[7];
    const float* W_V1 = (const float*)d_in[8],  *b_V1 = (const float*)d_in[9];
    const float* W_V2 = (const float*)d_in[10], *b_V2 = (const float*)d_in[11];
    const float* W_E1 = (const float*)d_in[12], *b_E1 = (const float*)d_in[13];
    const float* W_P1 = (const float*)d_in[14], *b_P1 = (const float*)d_in[15];
    const float* W_P2 = (const float*)d_in[16], *b_P2 = (const float*)d_in[17];
    const float* W_P3 = (const float*)d_in[18], *b_P3 = (const float*)d_in[19];
    const float* W_D1 = (const float*)d_in[20], *b_D1 = (const float*)d_in[21];
    const float* W_D2 = (const float*)d_in[22], *b_D2 = (const float*)d_in[23];
    const float* W_V  = (const float*)d_in[24], *b_V  = (const float*)d_in[25];
    const float* W_T  = (const float*)d_in[26], *b_T  = (const float*)d_in[27];
    float* out = (float*)d_out;

    cudaFuncSetAttribute(k_nodeg, cudaFuncAttributeMaxDynamicSharedMemorySize, SM_TOTAL);
    cudaFuncSetAttribute(k_edgeA, cudaFuncAttributeMaxDynamicSharedMemorySize, SM_TOTAL);
    cudaFuncSetAttribute(k_edgeB, cudaFuncAttributeMaxDynamicSharedMemorySize, SM_TOTAL);

    k_prep<<<640, 256>>>(W_V1, W_V2, W_P1, W_P2, W_P3, W_D1, W_D2, W_E1, W_V, W_T);
    k_count<<<EE / 256, 256>>>(smask, dst);
    k_nodeg<<<GRID_P, 256, SM_TOTAL>>>(h, p, dv, b_V1, b_V2, b_P1, b_P2, b_P3,
                                       b_D1, b_D2, b_T);
    k_edgeA<<<GRID_P, 256, SM_TOTAL>>>(e, src, dst, smask, b_E1, out + (size_t)NN * DD);
    k_edgeB<<<GRID_P, 256, SM_TOTAL>>>(h, b_V, src, dst);
    k_final<<<NN / 8, 256>>>(h, p, dv, dt, out);
}